// round 6
// baseline (speedup 1.0000x reference)
#include <cuda_runtime.h>
#include <cstdint>

#define NB      64
#define DMODEL  2048
#define DSSM    4096
#define NHEADS  64
#define HEADDIM 64
#define DSTATE  128
#define DINPROJ 8512   // 2*4096 + 2*128 + 64

// ---------------- scratch (device globals; no allocation) ----------------
__device__ __align__(16) int   g_xq [NB*512];        // hidden quantized, B-FRAGMENT-PERMUTED
__device__            float    g_xs [NB];
__device__ __align__(16) int   g_wq1[DINPROJ*512];   // W_in quantized, A-FRAGMENT-PERMUTED
__device__            float    g_ws1[DINPROJ];
__device__ __align__(16) float g_zx [NB*DINPROJ];    // zxbcdt fp32
__device__ __align__(16) float g_yraw[NB*DSSM];
__device__ __align__(16) int   g_yq [NB*1024];       // y quantized, B-FRAGMENT-PERMUTED
__device__            float    g_ys [NB];
__device__ __align__(16) int   g_wq2[DMODEL*1024];   // W_out quantized, A-FRAGMENT-PERMUTED
__device__            float    g_ws2[DMODEL];
__device__            int      g_xbcmax[NB];         // per-batch max|xBC| (float-as-int)
__device__            int      g_ymax  [NB];         // per-batch max|y_raw|

// ---------------- helpers ----------------
__device__ __forceinline__ int pack4(float a, float b, float c, float d, float s) {
    int q0 = (int)rintf(a / s);
    int q1 = (int)rintf(b / s);
    int q2 = (int)rintf(c / s);
    int q3 = (int)rintf(d / s);
    return (q0 & 0xFF) | ((q1 & 0xFF) << 8) | ((q2 & 0xFF) << 16) | (q3 << 24);
}

__device__ __forceinline__ void mma_s8(int* c, int a0, int a1, int a2, int a3,
                                       int b0, int b1) {
    asm volatile(
        "mma.sync.aligned.m16n8k32.row.col.s32.s8.s8.s32 "
        "{%0,%1,%2,%3}, {%4,%5,%6,%7}, {%8,%9}, {%0,%1,%2,%3};\n"
        : "+r"(c[0]), "+r"(c[1]), "+r"(c[2]), "+r"(c[3])
        : "r"(a0), "r"(a1), "r"(a2), "r"(a3), "r"(b0), "r"(b1));
}

// B-fragment scatter address (int index) for value covering k[4*j4 .. 4*j4+3] of column b.
__device__ __forceinline__ int bfrag_idx(int b, int j4) {
    int kt = j4 >> 4, comp = (j4 >> 2) & 3, c = j4 & 3;
    int nt = b >> 3, lane = ((b & 7) << 2) + c;
    return ((kt * 8 + nt) * 32 + lane) * 4 + comp;
}

// ---------------- W quantization device function (A-fragment-permuted) ----------------
template<int K>
__device__ __forceinline__ void qw_dev(const float* __restrict__ W, int4* __restrict__ Ap,
                                       float* __restrict__ ws, int bid,
                                       float* sm, float* ssc) {
    const int KT = K / 64;
    int t = threadIdx.x;
    int lane = t & 31, half = (t >> 5) & 1, ktb = t >> 6;   // ktb: 0..3
    int c = lane & 3, rl = (lane >> 2) + half * 8;          // local row 0..15
    int rowg = bid * 16 + rl;
    const float4* Wr = (const float4*)(W + (size_t)rowg * K);

    float m = 0.f;
    for (int kt = ktb; kt < KT; kt += 4) {
        #pragma unroll
        for (int j = 0; j < 4; j++) {
            float4 v = Wr[kt * 16 + c + j * 4];
            m = fmaxf(m, fmaxf(fmaxf(fabsf(v.x), fabsf(v.y)), fmaxf(fabsf(v.z), fabsf(v.w))));
        }
    }
    sm[t] = m; __syncthreads();
    if (t < 16) {
        float mm = 0.f;
        #pragma unroll
        for (int cc = 0; cc < 4; cc++)
            #pragma unroll
            for (int kb = 0; kb < 4; kb++)
                mm = fmaxf(mm, sm[((t & 7) << 2) + cc + ((t >> 3) << 5) + (kb << 6)]);
        float s = mm / 127.0f;
        if (s == 0.f) s = 1.f;
        ssc[t] = s;
        ws[bid * 16 + t] = s;
    }
    __syncthreads();
    float s = ssc[rl];
    int4* outb = Ap + (size_t)bid * KT * 64;
    for (int kt = ktb; kt < KT; kt += 4) {
        int q[4];
        #pragma unroll
        for (int j = 0; j < 4; j++) {
            float4 v = Wr[kt * 16 + c + j * 4];
            q[j] = pack4(v.x, v.y, v.z, v.w, s);
        }
        outb[kt * 64 + half * 32 + lane] = make_int4(q[0], q[1], q[2], q[3]);
    }
}

// ---------------- PREP: fused quant_x + W_in quant + W_out quant ----------------
// blocks [0,532): W_in rowblocks; [532,660): W_out rowblocks; [660,724): quant_x per batch
__global__ void __launch_bounds__(256)
prep_kernel(const float* __restrict__ hs, const float* __restrict__ Win,
            const float* __restrict__ Wout) {
    __shared__ float sm[256];
    __shared__ float ssc[16];
    int bid = blockIdx.x, t = threadIdx.x;
    if (bid < 532) {
        qw_dev<DMODEL>(Win, (int4*)g_wq1, g_ws1, bid, sm, ssc);
    } else if (bid < 660) {
        qw_dev<DSSM>(Wout, (int4*)g_wq2, g_ws2, bid - 532, sm, ssc);
    } else {
        int b = bid - 660;
        if (b == 0 && t < NB) { g_xbcmax[t] = 0; g_ymax[t] = 0; }
        const float* row = hs + b * DMODEL;
        float m = 0.f;
        for (int i = t; i < DMODEL; i += 256) m = fmaxf(m, fabsf(row[i]));
        sm[t] = m; __syncthreads();
        for (int s = 128; s > 0; s >>= 1) { if (t < s) sm[t] = fmaxf(sm[t], sm[t + s]); __syncthreads(); }
        float sc = sm[0] / 127.0f;
        if (sc == 0.f) sc = 1.f;
        if (t == 0) g_xs[b] = sc;
        const float4* row4 = (const float4*)row;
        for (int j4 = t; j4 < 512; j4 += 256) {
            float4 v = row4[j4];
            g_xq[bfrag_idx(b, j4)] = pack4(v.x, v.y, v.z, v.w, sc);
        }
    }
}

// ---------------- IMMA GEMM: 8 warps/block, A-fragment register double-buffer --------
template<int M, int K4, int NT, int NSPLIT, bool DOMAX>
__global__ void __launch_bounds__(256)
gemm_imma(const int4* __restrict__ Ap, const float* __restrict__ ws,
          const int4* __restrict__ xp, const float* __restrict__ xs,
          float* __restrict__ out) {
    const int KT = K4 / 16;
    int warp = threadIdx.x >> 5, lane = threadIdx.x & 31;
    int gw = blockIdx.x * 8 + warp;
    int rowblk = gw / NSPLIT;
    int nt0 = (gw % NSPLIT) * NT;
    int c = lane & 3, l4 = lane >> 2;

    int acc[NT][4];
    #pragma unroll
    for (int nt = 0; nt < NT; nt++)
        #pragma unroll
        for (int i = 0; i < 4; i++) acc[nt][i] = 0;

    const int4* Ab = Ap + (size_t)rowblk * KT * 64;
    int4 A0 = Ab[lane];
    int4 A1 = Ab[32 + lane];
    #pragma unroll 2
    for (int kt = 0; kt < KT; kt++) {
        int4 cA0 = A0, cA1 = A1;
        if (kt + 1 < KT) {                       // prefetch next A tile
            A0 = Ab[(kt + 1) * 64 + lane];
            A1 = Ab[(kt + 1) * 64 + 32 + lane];
        }
        int4 Bv[NT];
        #pragma unroll
        for (int nt = 0; nt < NT; nt++)
            Bv[nt] = xp[(kt * 8 + nt0 + nt) * 32 + lane];
        #pragma unroll
        for (int nt = 0; nt < NT; nt++)
            mma_s8(acc[nt], cA0.x, cA1.x, cA0.y, cA1.y, Bv[nt].x, Bv[nt].y);
        #pragma unroll
        for (int nt = 0; nt < NT; nt++)
            mma_s8(acc[nt], cA0.z, cA1.z, cA0.w, cA1.w, Bv[nt].z, Bv[nt].w);
    }

    int r0 = rowblk * 16 + l4;
    float w0 = ws[r0], w1 = ws[r0 + 8];
    #pragma unroll
    for (int nt = 0; nt < NT; nt++) {
        int n0 = (nt0 + nt) * 8 + c * 2;
        float s0 = xs[n0], s1 = xs[n0 + 1];
        float v00 = (float)acc[nt][0] * (w0 * s0);
        float v01 = (float)acc[nt][1] * (w0 * s1);
        float v10 = (float)acc[nt][2] * (w1 * s0);
        float v11 = (float)acc[nt][3] * (w1 * s1);
        out[(size_t)n0 * M + r0]           = v00;
        out[(size_t)(n0 + 1) * M + r0]     = v01;
        out[(size_t)n0 * M + r0 + 8]       = v10;
        out[(size_t)(n0 + 1) * M + r0 + 8] = v11;
        if (DOMAX && rowblk >= 256 && rowblk < 528) {   // rows 4096..8447 = xBC slice
            float m0 = fmaxf(fabsf(v00), fabsf(v10));   // batch n0
            float m1 = fmaxf(fabsf(v01), fabsf(v11));   // batch n0+1
            #pragma unroll
            for (int o = 4; o <= 16; o <<= 1) {         // reduce over l4 lanes
                m0 = fmaxf(m0, __shfl_xor_sync(0xFFFFFFFFu, m0, o));
                m1 = fmaxf(m1, __shfl_xor_sync(0xFFFFFFFFu, m1, o));
            }
            if (l4 == 0) {
                atomicMax(&g_xbcmax[n0],     __float_as_int(m0));
                atomicMax(&g_xbcmax[n0 + 1], __float_as_int(m1));
            }
        }
    }
}

// ---------------- K3: fused state readout + fake-quant + dt/exp + bcd ----------------
__global__ void __launch_bounds__(256)
state_kernel(const float* __restrict__ S, const float* __restrict__ dt_bias,
             const float* __restrict__ A_log) {
    __shared__ float smax[8];
    int warp = threadIdx.x >> 5, lane = threadIdx.x & 31;
    int wg = blockIdx.x * 8 + warp;  // 0..65535
    int pg = wg & 15;
    int h  = (wg >> 4) & 63;
    int b  = wg >> 10;               // constant within block

    const float* zb = g_zx + (size_t)b * DINPROJ;
    float sc = __int_as_float(g_xbcmax[b]) / 127.0f;
    if (sc == 0.f) sc = 1.f;

    float4 Cr = ((const float4*)(zb + 2 * DSSM + DSTATE))[lane];
    float4 C4 = make_float4(rintf(Cr.x / sc) * sc, rintf(Cr.y / sc) * sc,
                            rintf(Cr.z / sc) * sc, rintf(Cr.w / sc) * sc);

    const float* Sb = S + (((size_t)b * NHEADS + h) * HEADDIM + pg * 4) * DSTATE;
    float p[4];
    #pragma unroll
    for (int i = 0; i < 4; i++) {
        float4 s4 = ((const float4*)(Sb + i * DSTATE))[lane];
        p[i] = s4.x * C4.x + s4.y * C4.y + s4.z * C4.z + s4.w * C4.w;
    }
    float4 Br = ((const float4*)(zb + 2 * DSSM))[lane];
    float bc = (rintf(Br.x / sc) * sc) * C4.x + (rintf(Br.y / sc) * sc) * C4.y
             + (rintf(Br.z / sc) * sc) * C4.z + (rintf(Br.w / sc) * sc) * C4.w;
    #pragma unroll
    for (int o = 16; o; o >>= 1) {
        #pragma unroll
        for (int i = 0; i < 4; i++) p[i] += __shfl_xor_sync(0xFFFFFFFFu, p[i], o);
        bc += __shfl_xor_sync(0xFFFFFFFFu, bc, o);
    }
    float dtr = zb[2 * DSSM + 2 * DSTATE + h] + dt_bias[h];
    float dts;
    if (dtr < -2.0f)      dts = 0.0f;
    else if (dtr > 2.0f)  dts = dtr;
    else                  dts = 0.69314718055994531f + 0.5f * dtr
                                + (dtr * dtr) / 8.0f + (dtr * dtr * dtr) / 48.0f;
    float A  = -expf(A_log[h]);
    float xA = fmaxf(dts * A, -10000.0f);
    float x2 = xA * xA, x3 = x2 * xA, x4 = x3 * xA, x5 = x4 * xA;
    float e  = 1.0f + xA + x2 / 2.0f + x3 / 6.0f + x4 / 24.0f + x5 / 120.0f;
    e = fminf(fmaxf(e, 0.0f), 1.0f);

    float av = 0.f;
    if (lane < 4) {
        float sv = 0.f;
        #pragma unroll
        for (int i = 0; i < 4; i++) if (lane == i) sv = p[i];
        int   pp = pg * 4 + lane;
        float xv = zb[DSSM + h * HEADDIM + pp];
        xv = rintf(xv / sc) * sc;                       // fake-quanted x
        float v = e * sv + dts * bc * xv;
        g_yraw[b * DSSM + h * HEADDIM + pp] = v;
        av = fabsf(v);
    }
    #pragma unroll
    for (int o = 16; o; o >>= 1) av = fmaxf(av, __shfl_xor_sync(0xFFFFFFFFu, av, o));
    if (lane == 0) smax[warp] = av;
    __syncthreads();
    if (threadIdx.x == 0) {
        float m = smax[0];
        #pragma unroll
        for (int i = 1; i < 8; i++) m = fmaxf(m, smax[i]);
        atomicMax(&g_ymax[b], __float_as_int(m));
    }
}

// ---------------- K4: single-pass gated epilogue -> B-fragment int8 y ----------------
__global__ void __launch_bounds__(1024)
k4_kernel(const float* __restrict__ Dp) {
    __shared__ float red[32];
    __shared__ float s_s2;
    int b = blockIdx.x, t = threadIdx.x;
    int lane = t & 31;
    float s1 = __int_as_float(g_ymax[b]) / 127.0f;
    if (s1 == 0.f) s1 = 1.f;
    float sc = __int_as_float(g_xbcmax[b]) / 127.0f;
    if (sc == 0.f) sc = 1.f;

    const float4* yr4 = (const float4*)(g_yraw + b * DSSM);
    const float4* z4  = (const float4*)(g_zx + (size_t)b * DINPROJ);
    const float4* x4  = z4 + DSSM / 4;
    const float4* D4  = (const float4*)Dp;

    float4 yv = yr4[t], zv = z4[t], xv = x4[t], dv = D4[t];
    float4 y2;
    y2.x = (rintf(yv.x / s1) * s1 + dv.x * (rintf(xv.x / sc) * sc)) * fmaxf(zv.x, 0.f);
    y2.y = (rintf(yv.y / s1) * s1 + dv.y * (rintf(xv.y / sc) * sc)) * fmaxf(zv.y, 0.f);
    y2.z = (rintf(yv.z / s1) * s1 + dv.z * (rintf(xv.z / sc) * sc)) * fmaxf(zv.z, 0.f);
    y2.w = (rintf(yv.w / s1) * s1 + dv.w * (rintf(xv.w / sc) * sc)) * fmaxf(zv.w, 0.f);

    float m = fmaxf(fmaxf(fabsf(y2.x), fabsf(y2.y)), fmaxf(fabsf(y2.z), fabsf(y2.w)));
    #pragma unroll
    for (int o = 16; o; o >>= 1) m = fmaxf(m, __shfl_xor_sync(0xFFFFFFFFu, m, o));
    if (lane == 0) red[t >> 5] = m;
    __syncthreads();
    if (t < 32) {
        float mm = red[t];
        #pragma unroll
        for (int o = 16; o; o >>= 1) mm = fmaxf(mm, __shfl_xor_sync(0xFFFFFFFFu, mm, o));
        if (t == 0) { float s2 = mm / 127.0f; s_s2 = (s2 == 0.f) ? 1.f : s2; }
    }
    __syncthreads();
    float s2 = s_s2;
    if (t == 0) g_ys[b] = s2;   // 3rd fake_quant is idempotent at this grid

    g_yq[bfrag_idx(b, t)] = pack4(y2.x, y2.y, y2.z, y2.w, s2);
}

// ---------------- launch: 5 nodes, single stream ----------------
extern "C" void kernel_launch(void* const* d_in, const int* in_sizes, int n_in,
                              void* d_out, int out_size) {
    (void)in_sizes; (void)n_in; (void)out_size;
    const float* hs   = (const float*)d_in[0];
    const float* ssm  = (const float*)d_in[1];
    const float* Win  = (const float*)d_in[2];
    const float* dtb  = (const float*)d_in[3];
    const float* Alog = (const float*)d_in[4];
    const float* Dp   = (const float*)d_in[5];
    const float* Wout = (const float*)d_in[6];
    float* out = (float*)d_out;

    void *p_xq, *p_xs, *p_wq1, *p_ws1, *p_zx, *p_yq, *p_ys, *p_wq2, *p_ws2;
    cudaGetSymbolAddress(&p_xq,  g_xq);
    cudaGetSymbolAddress(&p_xs,  g_xs);
    cudaGetSymbolAddress(&p_wq1, g_wq1);
    cudaGetSymbolAddress(&p_ws1, g_ws1);
    cudaGetSymbolAddress(&p_zx,  g_zx);
    cudaGetSymbolAddress(&p_yq,  g_yq);
    cudaGetSymbolAddress(&p_ys,  g_ys);
    cudaGetSymbolAddress(&p_wq2, g_wq2);
    cudaGetSymbolAddress(&p_ws2, g_ws2);

    prep_kernel<<<724, 256>>>(hs, Win, Wout);
    // GEMM1: 532 rowblocks x NSPLIT=2 -> 1064 warps, 133 blocks of 8 warps
    gemm_imma<DINPROJ, 512, 4, 2, true><<<133, 256>>>(
        (const int4*)p_wq1, (const float*)p_ws1,
        (const int4*)p_xq, (const float*)p_xs, (float*)p_zx);
    state_kernel<<<(NB * NHEADS * 16) / 8, 256>>>(ssm, dtb, Alog);
    k4_kernel<<<NB, 1024>>>(Dp);
    // GEMM2: 128 rowblocks x NSPLIT=8 -> 1024 warps, 128 blocks of 8 warps
    gemm_imma<DMODEL, 1024, 1, 8, false><<<128, 256>>>(
        (const int4*)p_wq2, (const float*)p_ws2,
        (const int4*)p_yq, (const float*)p_ys, out);
}

// round 8
// speedup vs baseline: 1.0050x; 1.0050x over previous
#include <cuda_runtime.h>
#include <cstdint>

#define NB      64
#define DMODEL  2048
#define DSSM    4096
#define NHEADS  64
#define HEADDIM 64
#define DSTATE  128
#define DINPROJ 8512   // 2*4096 + 2*128 + 64

// ---------------- scratch (device globals; no allocation) ----------------
__device__ __align__(16) int   g_xq [NB*512];        // hidden quantized, B-FRAGMENT-PERMUTED
__device__            float    g_xs [NB];
__device__ __align__(16) int   g_wq1[DINPROJ*512];   // W_in quantized, A-FRAGMENT-PERMUTED
__device__            float    g_ws1[DINPROJ];
__device__ __align__(16) float g_zx [NB*DINPROJ];    // zxbcdt fp32
__device__ __align__(16) float g_yraw[NB*DSSM];
__device__ __align__(16) int   g_yq [NB*1024];       // y quantized, B-FRAGMENT-PERMUTED
__device__            float    g_ys [NB];
__device__ __align__(16) int   g_wq2[DMODEL*1024];   // W_out quantized, A-FRAGMENT-PERMUTED
__device__            float    g_ws2[DMODEL];
__device__            int      g_xbcmax[NB];         // per-batch max|xBC| (float-as-int)
__device__            int      g_ymax  [NB];         // per-batch max|y_raw|
__device__            int      g_cnt   [NB];         // per-batch arrival counter (self-reset)

// ---------------- helpers ----------------
__device__ __forceinline__ int pack4(float a, float b, float c, float d, float s) {
    int q0 = (int)rintf(a / s);
    int q1 = (int)rintf(b / s);
    int q2 = (int)rintf(c / s);
    int q3 = (int)rintf(d / s);
    return (q0 & 0xFF) | ((q1 & 0xFF) << 8) | ((q2 & 0xFF) << 16) | (q3 << 24);
}

__device__ __forceinline__ void mma_s8(int* c, int a0, int a1, int a2, int a3,
                                       int b0, int b1) {
    asm volatile(
        "mma.sync.aligned.m16n8k32.row.col.s32.s8.s8.s32 "
        "{%0,%1,%2,%3}, {%4,%5,%6,%7}, {%8,%9}, {%0,%1,%2,%3};\n"
        : "+r"(c[0]), "+r"(c[1]), "+r"(c[2]), "+r"(c[3])
        : "r"(a0), "r"(a1), "r"(a2), "r"(a3), "r"(b0), "r"(b1));
}

// B-fragment scatter address (int index) for value covering k[4*j4 .. 4*j4+3] of column b.
__device__ __forceinline__ int bfrag_idx(int b, int j4) {
    int kt = j4 >> 4, comp = (j4 >> 2) & 3, c = j4 & 3;
    int nt = b >> 3, lane = ((b & 7) << 2) + c;
    return ((kt * 8 + nt) * 32 + lane) * 4 + comp;
}

// ---------------- K0: quantize hidden states (+ reset atomics/counters) -------------
__global__ void quant_x_kernel(const float* __restrict__ hs) {
    __shared__ float sh[256];
    int b = blockIdx.x, t = threadIdx.x;
    if (b == 0 && t < NB) { g_xbcmax[t] = 0; g_ymax[t] = 0; g_cnt[t] = 0; }
    const float* row = hs + b * DMODEL;
    float m = 0.f;
    for (int i = t; i < DMODEL; i += 256) m = fmaxf(m, fabsf(row[i]));
    sh[t] = m; __syncthreads();
    for (int s = 128; s > 0; s >>= 1) { if (t < s) sh[t] = fmaxf(sh[t], sh[t + s]); __syncthreads(); }
    float sc = sh[0] / 127.0f;
    if (sc == 0.f) sc = 1.f;
    if (t == 0) g_xs[b] = sc;
    const float4* row4 = (const float4*)row;
    for (int j4 = t; j4 < 512; j4 += 256) {
        float4 v = row4[j4];
        g_xq[bfrag_idx(b, j4)] = pack4(v.x, v.y, v.z, v.w, sc);
    }
}

// ---------------- W quantization -> A-fragment-permuted layout ----------------
template<int K>
__global__ void __launch_bounds__(256)
quant_w_perm(const float* __restrict__ W, int4* __restrict__ Ap, float* __restrict__ ws) {
    const int KT = K / 64;
    __shared__ float sm[256];
    __shared__ float ssc[16];
    int t = threadIdx.x;
    int lane = t & 31, half = (t >> 5) & 1, ktb = t >> 6;   // ktb: 0..3
    int c = lane & 3, rl = (lane >> 2) + half * 8;          // local row 0..15
    int rowg = blockIdx.x * 16 + rl;
    const float4* Wr = (const float4*)(W + (size_t)rowg * K);

    float m = 0.f;
    for (int kt = ktb; kt < KT; kt += 4) {
        #pragma unroll
        for (int j = 0; j < 4; j++) {
            float4 v = Wr[kt * 16 + c + j * 4];
            m = fmaxf(m, fmaxf(fmaxf(fabsf(v.x), fabsf(v.y)), fmaxf(fabsf(v.z), fabsf(v.w))));
        }
    }
    sm[t] = m; __syncthreads();
    if (t < 16) {
        float mm = 0.f;
        #pragma unroll
        for (int cc = 0; cc < 4; cc++)
            #pragma unroll
            for (int kb = 0; kb < 4; kb++)
                mm = fmaxf(mm, sm[((t & 7) << 2) + cc + ((t >> 3) << 5) + (kb << 6)]);
        float s = mm / 127.0f;
        if (s == 0.f) s = 1.f;
        ssc[t] = s;
        ws[blockIdx.x * 16 + t] = s;
    }
    __syncthreads();
    float s = ssc[rl];
    int4* outb = Ap + (size_t)blockIdx.x * KT * 64;
    for (int kt = ktb; kt < KT; kt += 4) {
        int q[4];
        #pragma unroll
        for (int j = 0; j < 4; j++) {
            float4 v = Wr[kt * 16 + c + j * 4];
            q[j] = pack4(v.x, v.y, v.z, v.w, s);
        }
        outb[kt * 64 + half * 32 + lane] = make_int4(q[0], q[1], q[2], q[3]);
    }
}

// ---------------- IMMA GEMM: 8 warps/block, A-fragment register double-buffer --------
template<int M, int K4, int NT, int NSPLIT, bool DOMAX>
__global__ void __launch_bounds__(256)
gemm_imma(const int4* __restrict__ Ap, const float* __restrict__ ws,
          const int4* __restrict__ xp, const float* __restrict__ xs,
          float* __restrict__ out) {
    const int KT = K4 / 16;
    int warp = threadIdx.x >> 5, lane = threadIdx.x & 31;
    int gw = blockIdx.x * 8 + warp;
    int rowblk = gw / NSPLIT;
    int nt0 = (gw % NSPLIT) * NT;
    int c = lane & 3, l4 = lane >> 2;

    int acc[NT][4];
    #pragma unroll
    for (int nt = 0; nt < NT; nt++)
        #pragma unroll
        for (int i = 0; i < 4; i++) acc[nt][i] = 0;

    const int4* Ab = Ap + (size_t)rowblk * KT * 64;
    int4 A0 = Ab[lane];
    int4 A1 = Ab[32 + lane];
    #pragma unroll 2
    for (int kt = 0; kt < KT; kt++) {
        int4 cA0 = A0, cA1 = A1;
        if (kt + 1 < KT) {                       // prefetch next A tile
            A0 = Ab[(kt + 1) * 64 + lane];
            A1 = Ab[(kt + 1) * 64 + 32 + lane];
        }
        int4 Bv[NT];
        #pragma unroll
        for (int nt = 0; nt < NT; nt++)
            Bv[nt] = xp[(kt * 8 + nt0 + nt) * 32 + lane];
        #pragma unroll
        for (int nt = 0; nt < NT; nt++)
            mma_s8(acc[nt], cA0.x, cA1.x, cA0.y, cA1.y, Bv[nt].x, Bv[nt].y);
        #pragma unroll
        for (int nt = 0; nt < NT; nt++)
            mma_s8(acc[nt], cA0.z, cA1.z, cA0.w, cA1.w, Bv[nt].z, Bv[nt].w);
    }

    int r0 = rowblk * 16 + l4;
    float w0 = ws[r0], w1 = ws[r0 + 8];
    #pragma unroll
    for (int nt = 0; nt < NT; nt++) {
        int n0 = (nt0 + nt) * 8 + c * 2;
        float s0 = xs[n0], s1 = xs[n0 + 1];
        float v00 = (float)acc[nt][0] * (w0 * s0);
        float v01 = (float)acc[nt][1] * (w0 * s1);
        float v10 = (float)acc[nt][2] * (w1 * s0);
        float v11 = (float)acc[nt][3] * (w1 * s1);
        out[(size_t)n0 * M + r0]           = v00;
        out[(size_t)(n0 + 1) * M + r0]     = v01;
        out[(size_t)n0 * M + r0 + 8]       = v10;
        out[(size_t)(n0 + 1) * M + r0 + 8] = v11;
        if (DOMAX && rowblk >= 256 && rowblk < 528) {   // rows 4096..8447 = xBC slice
            float m0 = fmaxf(fabsf(v00), fabsf(v10));   // batch n0
            float m1 = fmaxf(fabsf(v01), fabsf(v11));   // batch n0+1
            #pragma unroll
            for (int o = 4; o <= 16; o <<= 1) {         // reduce over l4 lanes
                m0 = fmaxf(m0, __shfl_xor_sync(0xFFFFFFFFu, m0, o));
                m1 = fmaxf(m1, __shfl_xor_sync(0xFFFFFFFFu, m1, o));
            }
            if (l4 == 0) {
                atomicMax(&g_xbcmax[n0],     __float_as_int(m0));
                atomicMax(&g_xbcmax[n0 + 1], __float_as_int(m1));
            }
        }
    }
}

// ---------------- K3: state readout + fused k4 epilogue (last block per batch) -------
__global__ void __launch_bounds__(256)
state_kernel(const float* __restrict__ S, const float* __restrict__ dt_bias,
             const float* __restrict__ A_log, const float* __restrict__ Dp) {
    __shared__ float smax[8];
    __shared__ bool  slast;
    __shared__ float s_s2;
    int warp = threadIdx.x >> 5, lane = threadIdx.x & 31;
    int t  = threadIdx.x;
    int wg = blockIdx.x * 8 + warp;  // 0..65535
    int pg = wg & 15;
    int h  = (wg >> 4) & 63;
    int b  = wg >> 10;               // constant within block (128 blocks per batch)

    const float* zb = g_zx + (size_t)b * DINPROJ;
    float sc = __int_as_float(g_xbcmax[b]) / 127.0f;
    if (sc == 0.f) sc = 1.f;

    float4 Cr = ((const float4*)(zb + 2 * DSSM + DSTATE))[lane];
    float4 C4 = make_float4(rintf(Cr.x / sc) * sc, rintf(Cr.y / sc) * sc,
                            rintf(Cr.z / sc) * sc, rintf(Cr.w / sc) * sc);

    const float* Sb = S + (((size_t)b * NHEADS + h) * HEADDIM + pg * 4) * DSTATE;
    float p[4];
    #pragma unroll
    for (int i = 0; i < 4; i++) {
        float4 s4 = ((const float4*)(Sb + i * DSTATE))[lane];
        p[i] = s4.x * C4.x + s4.y * C4.y + s4.z * C4.z + s4.w * C4.w;
    }
    float4 Br = ((const float4*)(zb + 2 * DSSM))[lane];
    float bc = (rintf(Br.x / sc) * sc) * C4.x + (rintf(Br.y / sc) * sc) * C4.y
             + (rintf(Br.z / sc) * sc) * C4.z + (rintf(Br.w / sc) * sc) * C4.w;
    #pragma unroll
    for (int o = 16; o; o >>= 1) {
        #pragma unroll
        for (int i = 0; i < 4; i++) p[i] += __shfl_xor_sync(0xFFFFFFFFu, p[i], o);
        bc += __shfl_xor_sync(0xFFFFFFFFu, bc, o);
    }
    float dtr = zb[2 * DSSM + 2 * DSTATE + h] + dt_bias[h];
    float dts;
    if (dtr < -2.0f)      dts = 0.0f;
    else if (dtr > 2.0f)  dts = dtr;
    else                  dts = 0.69314718055994531f + 0.5f * dtr
                                + (dtr * dtr) / 8.0f + (dtr * dtr * dtr) / 48.0f;
    float A  = -expf(A_log[h]);
    float xA = fmaxf(dts * A, -10000.0f);
    float xA2 = xA * xA, xA3 = xA2 * xA, xA4 = xA3 * xA, xA5 = xA4 * xA;
    float e  = 1.0f + xA + xA2 / 2.0f + xA3 / 6.0f + xA4 / 24.0f + xA5 / 120.0f;
    e = fminf(fmaxf(e, 0.0f), 1.0f);

    float av = 0.f;
    if (lane < 4) {
        float sv = 0.f;
        #pragma unroll
        for (int i = 0; i < 4; i++) if (lane == i) sv = p[i];
        int   pp = pg * 4 + lane;
        float xv = zb[DSSM + h * HEADDIM + pp];
        xv = rintf(xv / sc) * sc;                       // fake-quanted x
        float v = e * sv + dts * bc * xv;
        g_yraw[b * DSSM + h * HEADDIM + pp] = v;
        av = fabsf(v);
    }
    #pragma unroll
    for (int o = 16; o; o >>= 1) av = fmaxf(av, __shfl_xor_sync(0xFFFFFFFFu, av, o));
    if (lane == 0) smax[warp] = av;
    __syncthreads();
    if (t == 0) {
        float m = smax[0];
        #pragma unroll
        for (int i = 1; i < 8; i++) m = fmaxf(m, smax[i]);
        atomicMax(&g_ymax[b], __float_as_int(m));
        __threadfence();                                 // y_raw + ymax visible before arrival
        int old = atomicAdd(&g_cnt[b], 1);
        slast = (old == 127);
    }
    __syncthreads();
    if (!slast) return;

    // ---- last block for batch b: full gated epilogue + quantization (former k4) ----
    __threadfence();                                     // acquire side of the counter
    float s1 = __int_as_float(atomicMax(&g_ymax[b], 0)) / 127.0f;
    if (s1 == 0.f) s1 = 1.f;
    const float4* yq4 = (const float4*)(g_yraw + b * DSSM);
    const float4* zq4 = (const float4*)zb;
    const float4* xq4 = zq4 + DSSM / 4;
    const float4* dq4 = (const float4*)Dp;

    float4 y2v[4];
    float m2 = 0.f;
    #pragma unroll
    for (int j = 0; j < 4; j++) {
        int i = t + j * 256;
        float4 yv = __ldcg(yq4 + i);                     // L2-coherent read of all blocks' writes
        float4 zv = zq4[i], xv = xq4[i], dv = dq4[i];
        float4 y2;
        y2.x = (rintf(yv.x / s1) * s1 + dv.x * (rintf(xv.x / sc) * sc)) * fmaxf(zv.x, 0.f);
        y2.y = (rintf(yv.y / s1) * s1 + dv.y * (rintf(xv.y / sc) * sc)) * fmaxf(zv.y, 0.f);
        y2.z = (rintf(yv.z / s1) * s1 + dv.z * (rintf(xv.z / sc) * sc)) * fmaxf(zv.z, 0.f);
        y2.w = (rintf(yv.w / s1) * s1 + dv.w * (rintf(xv.w / sc) * sc)) * fmaxf(zv.w, 0.f);
        y2v[j] = y2;
        m2 = fmaxf(m2, fmaxf(fmaxf(fabsf(y2.x), fabsf(y2.y)), fmaxf(fabsf(y2.z), fabsf(y2.w))));
    }
    #pragma unroll
    for (int o = 16; o; o >>= 1) m2 = fmaxf(m2, __shfl_xor_sync(0xFFFFFFFFu, m2, o));
    if (lane == 0) smax[warp] = m2;
    __syncthreads();
    if (t == 0) {
        float mm = smax[0];
        #pragma unroll
        for (int i = 1; i < 8; i++) mm = fmaxf(mm, smax[i]);
        float s2 = mm / 127.0f;
        s_s2 = (s2 == 0.f) ? 1.f : s2;
        g_ys[b] = s_s2;                                  // 3rd fake_quant idempotent
        g_cnt[b] = 0;                                    // self-reset for next replay
    }
    __syncthreads();
    float s2 = s_s2;
    #pragma unroll
    for (int j = 0; j < 4; j++) {
        int i = t + j * 256;
        g_yq[bfrag_idx(b, i)] = pack4(y2v[j].x, y2v[j].y, y2v[j].z, y2v[j].w, s2);
    }
}

// ---------------- launch: R4 fork topology, 6 kernels ----------------
extern "C" void kernel_launch(void* const* d_in, const int* in_sizes, int n_in,
                              void* d_out, int out_size) {
    (void)in_sizes; (void)n_in; (void)out_size;
    const float* hs   = (const float*)d_in[0];
    const float* ssm  = (const float*)d_in[1];
    const float* Win  = (const float*)d_in[2];
    const float* dtb  = (const float*)d_in[3];
    const float* Alog = (const float*)d_in[4];
    const float* Dp   = (const float*)d_in[5];
    const float* Wout = (const float*)d_in[6];
    float* out = (float*)d_out;

    void *p_xq, *p_xs, *p_wq1, *p_ws1, *p_zx, *p_yq, *p_ys, *p_wq2, *p_ws2;
    cudaGetSymbolAddress(&p_xq,  g_xq);
    cudaGetSymbolAddress(&p_xs,  g_xs);
    cudaGetSymbolAddress(&p_wq1, g_wq1);
    cudaGetSymbolAddress(&p_ws1, g_ws1);
    cudaGetSymbolAddress(&p_zx,  g_zx);
    cudaGetSymbolAddress(&p_yq,  g_yq);
    cudaGetSymbolAddress(&p_ys,  g_ys);
    cudaGetSymbolAddress(&p_wq2, g_wq2);
    cudaGetSymbolAddress(&p_ws2, g_ws2);

    // Streams/events created ONCE on the first (correctness, pre-capture) call and
    // reused during capture -> no allocation during capture (validated in R5).
    static cudaStream_t s1 = nullptr, s2 = nullptr;
    static cudaEvent_t ef, e1, e2;
    if (!s1) {
        cudaStreamCreateWithFlags(&s1, cudaStreamNonBlocking);
        cudaStreamCreateWithFlags(&s2, cudaStreamNonBlocking);
        cudaEventCreateWithFlags(&ef, cudaEventDisableTiming);
        cudaEventCreateWithFlags(&e1, cudaEventDisableTiming);
        cudaEventCreateWithFlags(&e2, cudaEventDisableTiming);
    }

    cudaEventRecord(ef, 0);
    cudaStreamWaitEvent(s1, ef, 0);
    cudaStreamWaitEvent(s2, ef, 0);

    // branch s1: W_in quant (joins before gemm1)
    quant_w_perm<DMODEL><<<DINPROJ / 16, 256, 0, s1>>>(Win, (int4*)p_wq1, (float*)p_ws1);
    cudaEventRecord(e1, s1);
    // branch s2: W_out quant (joins before gemm2 — fully off critical path)
    quant_w_perm<DSSM><<<DMODEL / 16, 256, 0, s2>>>(Wout, (int4*)p_wq2, (float*)p_ws2);
    cudaEventRecord(e2, s2);

    // main chain
    quant_x_kernel<<<NB, 256>>>(hs);
    cudaStreamWaitEvent(0, e1, 0);
    gemm_imma<DINPROJ, 512, 4, 2, true><<<133, 256>>>(
        (const int4*)p_wq1, (const float*)p_ws1,
        (const int4*)p_xq, (const float*)p_xs, (float*)p_zx);
    state_kernel<<<(NB * NHEADS * 16) / 8, 256>>>(ssm, dtb, Alog, Dp);
    cudaStreamWaitEvent(0, e2, 0);
    gemm_imma<DMODEL, 1024, 1, 8, false><<<128, 256>>>(
        (const int4*)p_wq2, (const float*)p_ws2,
        (const int4*)p_yq, (const float*)p_ys, out);
}

// round 9
// speedup vs baseline: 1.0602x; 1.0549x over previous
#include <cuda_runtime.h>
#include <cstdint>

#define NB      64
#define DMODEL  2048
#define DSSM    4096
#define NHEADS  64
#define HEADDIM 64
#define DSTATE  128
#define DINPROJ 8512   // 2*4096 + 2*128 + 64

// ---------------- scratch (device globals; no allocation) ----------------
__device__ __align__(16) int   g_xq [NB*512];        // hidden quantized, B-FRAGMENT-PERMUTED
__device__            float    g_xs [NB];
__device__ __align__(16) int   g_wq1[DINPROJ*512];   // W_in quantized, A-FRAGMENT-PERMUTED
__device__            float    g_ws1[DINPROJ];
__device__ __align__(16) float g_zx [NB*DINPROJ];    // zxbcdt fp32
__device__ __align__(16) float g_yraw[NB*DSSM];
__device__ __align__(16) int   g_yq [NB*1024];       // y quantized, B-FRAGMENT-PERMUTED
__device__            float    g_ys [NB];
__device__ __align__(16) int   g_wq2[DMODEL*1024];   // W_out quantized, A-FRAGMENT-PERMUTED
__device__            float    g_ws2[DMODEL];
__device__            int      g_xbcmax[NB];         // per-batch max|xBC| (float-as-int)
__device__            int      g_ymax  [NB];         // per-batch max|y_raw|
__device__            int      g_cnt   [NB];         // per-batch arrival counter (self-reset)

// ---------------- helpers ----------------
__device__ __forceinline__ int pack4(float a, float b, float c, float d, float s) {
    int q0 = (int)rintf(a / s);
    int q1 = (int)rintf(b / s);
    int q2 = (int)rintf(c / s);
    int q3 = (int)rintf(d / s);
    return (q0 & 0xFF) | ((q1 & 0xFF) << 8) | ((q2 & 0xFF) << 16) | (q3 << 24);
}

__device__ __forceinline__ void mma_s8(int* c, int a0, int a1, int a2, int a3,
                                       int b0, int b1) {
    asm volatile(
        "mma.sync.aligned.m16n8k32.row.col.s32.s8.s8.s32 "
        "{%0,%1,%2,%3}, {%4,%5,%6,%7}, {%8,%9}, {%0,%1,%2,%3};\n"
        : "+r"(c[0]), "+r"(c[1]), "+r"(c[2]), "+r"(c[3])
        : "r"(a0), "r"(a1), "r"(a2), "r"(a3), "r"(b0), "r"(b1));
}

// B-fragment scatter address (int index) for value covering k[4*j4 .. 4*j4+3] of column b.
__device__ __forceinline__ int bfrag_idx(int b, int j4) {
    int kt = j4 >> 4, comp = (j4 >> 2) & 3, c = j4 & 3;
    int nt = b >> 3, lane = ((b & 7) << 2) + c;
    return ((kt * 8 + nt) * 32 + lane) * 4 + comp;
}

// ---------------- K0: quantize hidden states (+ reset atomics/counters) -------------
__global__ void quant_x_kernel(const float* __restrict__ hs) {
    __shared__ float sh[256];
    int b = blockIdx.x, t = threadIdx.x;
    if (b == 0 && t < NB) { g_xbcmax[t] = 0; g_ymax[t] = 0; g_cnt[t] = 0; }
    const float* row = hs + b * DMODEL;
    float m = 0.f;
    for (int i = t; i < DMODEL; i += 256) m = fmaxf(m, fabsf(row[i]));
    sh[t] = m; __syncthreads();
    for (int s = 128; s > 0; s >>= 1) { if (t < s) sh[t] = fmaxf(sh[t], sh[t + s]); __syncthreads(); }
    float sc = sh[0] / 127.0f;
    if (sc == 0.f) sc = 1.f;
    if (t == 0) g_xs[b] = sc;
    const float4* row4 = (const float4*)row;
    for (int j4 = t; j4 < 512; j4 += 256) {
        float4 v = row4[j4];
        g_xq[bfrag_idx(b, j4)] = pack4(v.x, v.y, v.z, v.w, sc);
    }
}

// ---------------- W quantization -> A-fragment-permuted layout ----------------
template<int K>
__global__ void __launch_bounds__(256)
quant_w_perm(const float* __restrict__ W, int4* __restrict__ Ap, float* __restrict__ ws) {
    const int KT = K / 64;
    __shared__ float sm[256];
    __shared__ float ssc[16];
    int t = threadIdx.x;
    int lane = t & 31, half = (t >> 5) & 1, ktb = t >> 6;   // ktb: 0..3
    int c = lane & 3, rl = (lane >> 2) + half * 8;          // local row 0..15
    int rowg = blockIdx.x * 16 + rl;
    const float4* Wr = (const float4*)(W + (size_t)rowg * K);

    float m = 0.f;
    for (int kt = ktb; kt < KT; kt += 4) {
        #pragma unroll
        for (int j = 0; j < 4; j++) {
            float4 v = Wr[kt * 16 + c + j * 4];
            m = fmaxf(m, fmaxf(fmaxf(fabsf(v.x), fabsf(v.y)), fmaxf(fabsf(v.z), fabsf(v.w))));
        }
    }
    sm[t] = m; __syncthreads();
    if (t < 16) {
        float mm = 0.f;
        #pragma unroll
        for (int cc = 0; cc < 4; cc++)
            #pragma unroll
            for (int kb = 0; kb < 4; kb++)
                mm = fmaxf(mm, sm[((t & 7) << 2) + cc + ((t >> 3) << 5) + (kb << 6)]);
        float s = mm / 127.0f;
        if (s == 0.f) s = 1.f;
        ssc[t] = s;
        ws[blockIdx.x * 16 + t] = s;
    }
    __syncthreads();
    float s = ssc[rl];
    int4* outb = Ap + (size_t)blockIdx.x * KT * 64;
    for (int kt = ktb; kt < KT; kt += 4) {
        int q[4];
        #pragma unroll
        for (int j = 0; j < 4; j++) {
            float4 v = Wr[kt * 16 + c + j * 4];
            q[j] = pack4(v.x, v.y, v.z, v.w, s);
        }
        outb[kt * 64 + half * 32 + lane] = make_int4(q[0], q[1], q[2], q[3]);
    }
}

// ---------------- IMMA GEMM: PF-deep A-register pipeline ----------------
template<int M, int K4, int NT, int NSPLIT, bool DOMAX, int PF>
__global__ void __launch_bounds__(256)
gemm_imma(const int4* __restrict__ Ap, const float* __restrict__ ws,
          const int4* __restrict__ xp, const float* __restrict__ xs,
          float* __restrict__ out) {
    const int KT = K4 / 16;
    static_assert(KT % PF == 0, "KT must be divisible by PF");
    int warp = threadIdx.x >> 5, lane = threadIdx.x & 31;
    int gw = blockIdx.x * 8 + warp;
    int rowblk = gw / NSPLIT;
    int nt0 = (gw % NSPLIT) * NT;
    int c = lane & 3, l4 = lane >> 2;

    int acc[NT][4];
    #pragma unroll
    for (int nt = 0; nt < NT; nt++)
        #pragma unroll
        for (int i = 0; i < 4; i++) acc[nt][i] = 0;

    const int4* Ab = Ap + (size_t)rowblk * KT * 64;
    int4 Abuf[PF][2];
    #pragma unroll
    for (int j = 0; j < PF; j++) {
        Abuf[j][0] = Ab[j * 64 + lane];
        Abuf[j][1] = Ab[j * 64 + 32 + lane];
    }

    #pragma unroll 1
    for (int kt0 = 0; kt0 < KT; kt0 += PF) {
        #pragma unroll
        for (int j = 0; j < PF; j++) {
            int kt = kt0 + j;
            int4 cA0 = Abuf[j][0], cA1 = Abuf[j][1];
            if (kt + PF < KT) {                   // refill slot j, PF tiles ahead
                Abuf[j][0] = Ab[(kt + PF) * 64 + lane];
                Abuf[j][1] = Ab[(kt + PF) * 64 + 32 + lane];
            }
            int4 Bv[NT];
            #pragma unroll
            for (int nt = 0; nt < NT; nt++)
                Bv[nt] = xp[(kt * 8 + nt0 + nt) * 32 + lane];
            #pragma unroll
            for (int nt = 0; nt < NT; nt++)
                mma_s8(acc[nt], cA0.x, cA1.x, cA0.y, cA1.y, Bv[nt].x, Bv[nt].y);
            #pragma unroll
            for (int nt = 0; nt < NT; nt++)
                mma_s8(acc[nt], cA0.z, cA1.z, cA0.w, cA1.w, Bv[nt].z, Bv[nt].w);
        }
    }

    int r0 = rowblk * 16 + l4;
    float w0 = ws[r0], w1 = ws[r0 + 8];
    #pragma unroll
    for (int nt = 0; nt < NT; nt++) {
        int n0 = (nt0 + nt) * 8 + c * 2;
        float s0 = xs[n0], s1 = xs[n0 + 1];
        float v00 = (float)acc[nt][0] * (w0 * s0);
        float v01 = (float)acc[nt][1] * (w0 * s1);
        float v10 = (float)acc[nt][2] * (w1 * s0);
        float v11 = (float)acc[nt][3] * (w1 * s1);
        out[(size_t)n0 * M + r0]           = v00;
        out[(size_t)(n0 + 1) * M + r0]     = v01;
        out[(size_t)n0 * M + r0 + 8]       = v10;
        out[(size_t)(n0 + 1) * M + r0 + 8] = v11;
        if (DOMAX && rowblk >= 256 && rowblk < 528) {   // rows 4096..8447 = xBC slice
            float m0 = fmaxf(fabsf(v00), fabsf(v10));   // batch n0
            float m1 = fmaxf(fabsf(v01), fabsf(v11));   // batch n0+1
            #pragma unroll
            for (int o = 4; o <= 16; o <<= 1) {         // reduce over l4 lanes
                m0 = fmaxf(m0, __shfl_xor_sync(0xFFFFFFFFu, m0, o));
                m1 = fmaxf(m1, __shfl_xor_sync(0xFFFFFFFFu, m1, o));
            }
            if (l4 == 0) {
                atomicMax(&g_xbcmax[n0],     __float_as_int(m0));
                atomicMax(&g_xbcmax[n0 + 1], __float_as_int(m1));
            }
        }
    }
}

// ---------------- K3: state readout + fused k4 epilogue (last block per batch) -------
__global__ void __launch_bounds__(256)
state_kernel(const float* __restrict__ S, const float* __restrict__ dt_bias,
             const float* __restrict__ A_log, const float* __restrict__ Dp) {
    __shared__ float smax[8];
    __shared__ bool  slast;
    __shared__ float s_s2;
    int warp = threadIdx.x >> 5, lane = threadIdx.x & 31;
    int t  = threadIdx.x;
    int wg = blockIdx.x * 8 + warp;  // 0..65535
    int pg = wg & 15;
    int h  = (wg >> 4) & 63;
    int b  = wg >> 10;               // constant within block (128 blocks per batch)

    const float* zb = g_zx + (size_t)b * DINPROJ;
    float sc = __int_as_float(g_xbcmax[b]) / 127.0f;
    if (sc == 0.f) sc = 1.f;

    float4 Cr = ((const float4*)(zb + 2 * DSSM + DSTATE))[lane];
    float4 C4 = make_float4(rintf(Cr.x / sc) * sc, rintf(Cr.y / sc) * sc,
                            rintf(Cr.z / sc) * sc, rintf(Cr.w / sc) * sc);

    const float* Sb = S + (((size_t)b * NHEADS + h) * HEADDIM + pg * 4) * DSTATE;
    float p[4];
    #pragma unroll
    for (int i = 0; i < 4; i++) {
        float4 s4 = ((const float4*)(Sb + i * DSTATE))[lane];
        p[i] = s4.x * C4.x + s4.y * C4.y + s4.z * C4.z + s4.w * C4.w;
    }
    float4 Br = ((const float4*)(zb + 2 * DSSM))[lane];
    float bc = (rintf(Br.x / sc) * sc) * C4.x + (rintf(Br.y / sc) * sc) * C4.y
             + (rintf(Br.z / sc) * sc) * C4.z + (rintf(Br.w / sc) * sc) * C4.w;
    #pragma unroll
    for (int o = 16; o; o >>= 1) {
        #pragma unroll
        for (int i = 0; i < 4; i++) p[i] += __shfl_xor_sync(0xFFFFFFFFu, p[i], o);
        bc += __shfl_xor_sync(0xFFFFFFFFu, bc, o);
    }
    float dtr = zb[2 * DSSM + 2 * DSTATE + h] + dt_bias[h];
    float dts;
    if (dtr < -2.0f)      dts = 0.0f;
    else if (dtr > 2.0f)  dts = dtr;
    else                  dts = 0.69314718055994531f + 0.5f * dtr
                                + (dtr * dtr) / 8.0f + (dtr * dtr * dtr) / 48.0f;
    float A  = -expf(A_log[h]);
    float xA = fmaxf(dts * A, -10000.0f);
    float xA2 = xA * xA, xA3 = xA2 * xA, xA4 = xA3 * xA, xA5 = xA4 * xA;
    float e  = 1.0f + xA + xA2 / 2.0f + xA3 / 6.0f + xA4 / 24.0f + xA5 / 120.0f;
    e = fminf(fmaxf(e, 0.0f), 1.0f);

    float av = 0.f;
    if (lane < 4) {
        float sv = 0.f;
        #pragma unroll
        for (int i = 0; i < 4; i++) if (lane == i) sv = p[i];
        int   pp = pg * 4 + lane;
        float xv = zb[DSSM + h * HEADDIM + pp];
        xv = rintf(xv / sc) * sc;                       // fake-quanted x
        float v = e * sv + dts * bc * xv;
        g_yraw[b * DSSM + h * HEADDIM + pp] = v;
        av = fabsf(v);
    }
    #pragma unroll
    for (int o = 16; o; o >>= 1) av = fmaxf(av, __shfl_xor_sync(0xFFFFFFFFu, av, o));
    if (lane == 0) smax[warp] = av;
    __syncthreads();
    if (t == 0) {
        float m = smax[0];
        #pragma unroll
        for (int i = 1; i < 8; i++) m = fmaxf(m, smax[i]);
        atomicMax(&g_ymax[b], __float_as_int(m));
        __threadfence();                                 // y_raw + ymax visible before arrival
        int old = atomicAdd(&g_cnt[b], 1);
        slast = (old == 127);
    }
    __syncthreads();
    if (!slast) return;

    // ---- last block for batch b: full gated epilogue + quantization (former k4) ----
    __threadfence();                                     // acquire side of the counter
    float s1 = __int_as_float(atomicMax(&g_ymax[b], 0)) / 127.0f;
    if (s1 == 0.f) s1 = 1.f;
    const float4* yq4 = (const float4*)(g_yraw + b * DSSM);
    const float4* zq4 = (const float4*)zb;
    const float4* xq4 = zq4 + DSSM / 4;
    const float4* dq4 = (const float4*)Dp;

    float4 y2v[4];
    float m2 = 0.f;
    #pragma unroll
    for (int j = 0; j < 4; j++) {
        int i = t + j * 256;
        float4 yv = __ldcg(yq4 + i);                     // L2-coherent read of all blocks' writes
        float4 zv = zq4[i], xv = xq4[i], dv = dq4[i];
        float4 y2;
        y2.x = (rintf(yv.x / s1) * s1 + dv.x * (rintf(xv.x / sc) * sc)) * fmaxf(zv.x, 0.f);
        y2.y = (rintf(yv.y / s1) * s1 + dv.y * (rintf(xv.y / sc) * sc)) * fmaxf(zv.y, 0.f);
        y2.z = (rintf(yv.z / s1) * s1 + dv.z * (rintf(xv.z / sc) * sc)) * fmaxf(zv.z, 0.f);
        y2.w = (rintf(yv.w / s1) * s1 + dv.w * (rintf(xv.w / sc) * sc)) * fmaxf(zv.w, 0.f);
        y2v[j] = y2;
        m2 = fmaxf(m2, fmaxf(fmaxf(fabsf(y2.x), fabsf(y2.y)), fmaxf(fabsf(y2.z), fabsf(y2.w))));
    }
    #pragma unroll
    for (int o = 16; o; o >>= 1) m2 = fmaxf(m2, __shfl_xor_sync(0xFFFFFFFFu, m2, o));
    if (lane == 0) smax[warp] = m2;
    __syncthreads();
    if (t == 0) {
        float mm = smax[0];
        #pragma unroll
        for (int i = 1; i < 8; i++) mm = fmaxf(mm, smax[i]);
        float s2 = mm / 127.0f;
        s_s2 = (s2 == 0.f) ? 1.f : s2;
        g_ys[b] = s_s2;                                  // 3rd fake_quant idempotent
        g_cnt[b] = 0;                                    // self-reset for next replay
    }
    __syncthreads();
    float s2 = s_s2;
    #pragma unroll
    for (int j = 0; j < 4; j++) {
        int i = t + j * 256;
        g_yq[bfrag_idx(b, i)] = pack4(y2v[j].x, y2v[j].y, y2v[j].z, y2v[j].w, s2);
    }
}

// ---------------- launch: fork topology, 6 kernels ----------------
extern "C" void kernel_launch(void* const* d_in, const int* in_sizes, int n_in,
                              void* d_out, int out_size) {
    (void)in_sizes; (void)n_in; (void)out_size;
    const float* hs   = (const float*)d_in[0];
    const float* ssm  = (const float*)d_in[1];
    const float* Win  = (const float*)d_in[2];
    const float* dtb  = (const float*)d_in[3];
    const float* Alog = (const float*)d_in[4];
    const float* Dp   = (const float*)d_in[5];
    const float* Wout = (const float*)d_in[6];
    float* out = (float*)d_out;

    void *p_xq, *p_xs, *p_wq1, *p_ws1, *p_zx, *p_yq, *p_ys, *p_wq2, *p_ws2;
    cudaGetSymbolAddress(&p_xq,  g_xq);
    cudaGetSymbolAddress(&p_xs,  g_xs);
    cudaGetSymbolAddress(&p_wq1, g_wq1);
    cudaGetSymbolAddress(&p_ws1, g_ws1);
    cudaGetSymbolAddress(&p_zx,  g_zx);
    cudaGetSymbolAddress(&p_yq,  g_yq);
    cudaGetSymbolAddress(&p_ys,  g_ys);
    cudaGetSymbolAddress(&p_wq2, g_wq2);
    cudaGetSymbolAddress(&p_ws2, g_ws2);

    // Streams/events created ONCE on the first (correctness, pre-capture) call and
    // reused during capture -> no allocation during capture (validated in R5).
    static cudaStream_t s1 = nullptr, s2 = nullptr;
    static cudaEvent_t ef, e1, e2;
    if (!s1) {
        cudaStreamCreateWithFlags(&s1, cudaStreamNonBlocking);
        cudaStreamCreateWithFlags(&s2, cudaStreamNonBlocking);
        cudaEventCreateWithFlags(&ef, cudaEventDisableTiming);
        cudaEventCreateWithFlags(&e1, cudaEventDisableTiming);
        cudaEventCreateWithFlags(&e2, cudaEventDisableTiming);
    }

    cudaEventRecord(ef, 0);
    cudaStreamWaitEvent(s1, ef, 0);
    cudaStreamWaitEvent(s2, ef, 0);

    // branch s1: W_in quant (joins before gemm1)
    quant_w_perm<DMODEL><<<DINPROJ / 16, 256, 0, s1>>>(Win, (int4*)p_wq1, (float*)p_ws1);
    cudaEventRecord(e1, s1);
    // branch s2: W_out quant (joins before gemm2 — fully off critical path)
    quant_w_perm<DSSM><<<DMODEL / 16, 256, 0, s2>>>(Wout, (int4*)p_wq2, (float*)p_ws2);
    cudaEventRecord(e2, s2);

    // main chain
    quant_x_kernel<<<NB, 256>>>(hs);
    cudaStreamWaitEvent(0, e1, 0);
    gemm_imma<DINPROJ, 512, 4, 2, true, 4><<<133, 256>>>(
        (const int4*)p_wq1, (const float*)p_ws1,
        (const int4*)p_xq, (const float*)p_xs, (float*)p_zx);
    state_kernel<<<(NB * NHEADS * 16) / 8, 256>>>(ssm, dtb, Alog, Dp);
    cudaStreamWaitEvent(0, e2, 0);
    gemm_imma<DMODEL, 1024, 1, 8, false, 4><<<128, 256>>>(
        (const int4*)p_wq2, (const float*)p_ws2,
        (const int4*)p_yq, (const float*)p_ys, out);
}

// round 10
// speedup vs baseline: 1.1077x; 1.0448x over previous
#include <cuda_runtime.h>
#include <cstdint>

#define NB      64
#define DMODEL  2048
#define DSSM    4096
#define NHEADS  64
#define HEADDIM 64
#define DSTATE  128
#define DINPROJ 8512   // 2*4096 + 2*128 + 64

// ---------------- scratch (device globals; no allocation) ----------------
__device__ __align__(16) int   g_xq [NB*512];        // hidden quantized, B-FRAGMENT-PERMUTED
__device__            float    g_xs [NB];
__device__ __align__(16) int   g_wq1[DINPROJ*512];   // W_in quantized, A-FRAGMENT-PERMUTED
__device__            float    g_ws1[DINPROJ];
__device__ __align__(16) float g_zx [NB*DINPROJ];    // zxbcdt fp32
__device__ __align__(16) float g_yraw[NB*DSSM];
__device__ __align__(16) int   g_yq [NB*1024];       // y quantized, B-FRAGMENT-PERMUTED
__device__            float    g_ys [NB];
__device__ __align__(16) int   g_wq2[DMODEL*1024];   // W_out quantized, A-FRAGMENT-PERMUTED
__device__            float    g_ws2[DMODEL];
__device__            int      g_xbcmax[NB];         // per-batch max|xBC| (float-as-int)
__device__            int      g_ymax  [NB];         // per-batch max|y_raw|
__device__            int      g_cnt   [NB];         // per-batch arrival counter (self-reset)

// ---------------- helpers ----------------
__device__ __forceinline__ int pack4(float a, float b, float c, float d, float s) {
    int q0 = (int)rintf(a / s);
    int q1 = (int)rintf(b / s);
    int q2 = (int)rintf(c / s);
    int q3 = (int)rintf(d / s);
    return (q0 & 0xFF) | ((q1 & 0xFF) << 8) | ((q2 & 0xFF) << 16) | (q3 << 24);
}

__device__ __forceinline__ void mma_s8(int* c, int a0, int a1, int a2, int a3,
                                       int b0, int b1) {
    asm volatile(
        "mma.sync.aligned.m16n8k32.row.col.s32.s8.s8.s32 "
        "{%0,%1,%2,%3}, {%4,%5,%6,%7}, {%8,%9}, {%0,%1,%2,%3};\n"
        : "+r"(c[0]), "+r"(c[1]), "+r"(c[2]), "+r"(c[3])
        : "r"(a0), "r"(a1), "r"(a2), "r"(a3), "r"(b0), "r"(b1));
}

// B-fragment scatter address (int index) for value covering k[4*j4 .. 4*j4+3] of column b.
__device__ __forceinline__ int bfrag_idx(int b, int j4) {
    int kt = j4 >> 4, comp = (j4 >> 2) & 3, c = j4 & 3;
    int nt = b >> 3, lane = ((b & 7) << 2) + c;
    return ((kt * 8 + nt) * 32 + lane) * 4 + comp;
}

// ---------------- W quantization device function -> A-fragment-permuted layout -------
template<int K>
__device__ __forceinline__ void qw_dev(const float* __restrict__ W, int4* __restrict__ Ap,
                                       float* __restrict__ ws, int bid,
                                       float* sm, float* ssc) {
    const int KT = K / 64;
    int t = threadIdx.x;
    int lane = t & 31, half = (t >> 5) & 1, ktb = t >> 6;   // ktb: 0..3
    int c = lane & 3, rl = (lane >> 2) + half * 8;          // local row 0..15
    int rowg = bid * 16 + rl;
    const float4* Wr = (const float4*)(W + (size_t)rowg * K);

    float m = 0.f;
    for (int kt = ktb; kt < KT; kt += 4) {
        #pragma unroll
        for (int j = 0; j < 4; j++) {
            float4 v = Wr[kt * 16 + c + j * 4];
            m = fmaxf(m, fmaxf(fmaxf(fabsf(v.x), fabsf(v.y)), fmaxf(fabsf(v.z), fabsf(v.w))));
        }
    }
    sm[t] = m; __syncthreads();
    if (t < 16) {
        float mm = 0.f;
        #pragma unroll
        for (int cc = 0; cc < 4; cc++)
            #pragma unroll
            for (int kb = 0; kb < 4; kb++)
                mm = fmaxf(mm, sm[((t & 7) << 2) + cc + ((t >> 3) << 5) + (kb << 6)]);
        float s = mm / 127.0f;
        if (s == 0.f) s = 1.f;
        ssc[t] = s;
        ws[bid * 16 + t] = s;
    }
    __syncthreads();
    float s = ssc[rl];
    int4* outb = Ap + (size_t)bid * KT * 64;
    for (int kt = ktb; kt < KT; kt += 4) {
        int q[4];
        #pragma unroll
        for (int j = 0; j < 4; j++) {
            float4 v = Wr[kt * 16 + c + j * 4];
            q[j] = pack4(v.x, v.y, v.z, v.w, s);
        }
        outb[kt * 64 + half * 32 + lane] = make_int4(q[0], q[1], q[2], q[3]);
    }
}

// ---------------- PREP1 (main stream): W_in quant + quant_x fused ----------------
// blocks [0,532): W_in rowblocks; [532,596): quant_x per batch
__global__ void __launch_bounds__(256)
prep1_kernel(const float* __restrict__ hs, const float* __restrict__ Win) {
    __shared__ float sm[256];
    __shared__ float ssc[16];
    int bid = blockIdx.x, t = threadIdx.x;
    if (bid < 532) {
        qw_dev<DMODEL>(Win, (int4*)g_wq1, g_ws1, bid, sm, ssc);
        return;
    }
    int b = bid - 532;
    if (b == 0 && t < NB) { g_xbcmax[t] = 0; g_ymax[t] = 0; g_cnt[t] = 0; }
    const float* row = hs + b * DMODEL;
    float m = 0.f;
    for (int i = t; i < DMODEL; i += 256) m = fmaxf(m, fabsf(row[i]));
    sm[t] = m; __syncthreads();
    for (int s = 128; s > 0; s >>= 1) { if (t < s) sm[t] = fmaxf(sm[t], sm[t + s]); __syncthreads(); }
    float sc = sm[0] / 127.0f;
    if (sc == 0.f) sc = 1.f;
    if (t == 0) g_xs[b] = sc;
    const float4* row4 = (const float4*)row;
    for (int j4 = t; j4 < 512; j4 += 256) {
        float4 v = row4[j4];
        g_xq[bfrag_idx(b, j4)] = pack4(v.x, v.y, v.z, v.w, sc);
    }
}

// ---------------- W_out quantization (side stream) ----------------
__global__ void __launch_bounds__(256)
quant_w2_kernel(const float* __restrict__ Wout) {
    __shared__ float sm[256];
    __shared__ float ssc[16];
    qw_dev<DSSM>(Wout, (int4*)g_wq2, g_ws2, blockIdx.x, sm, ssc);
}

// ---------------- IMMA GEMM: PF-deep A+B register pipeline ----------------
template<int M, int K4, int NT, int NSPLIT, bool DOMAX, int PF>
__global__ void __launch_bounds__(256)
gemm_imma(const int4* __restrict__ Ap, const float* __restrict__ ws,
          const int4* __restrict__ xp, const float* __restrict__ xs,
          float* __restrict__ out) {
    const int KT = K4 / 16;
    static_assert(KT % PF == 0, "KT must be divisible by PF");
    int warp = threadIdx.x >> 5, lane = threadIdx.x & 31;
    int gw = blockIdx.x * 8 + warp;
    int rowblk = gw / NSPLIT;
    int nt0 = (gw % NSPLIT) * NT;
    int c = lane & 3, l4 = lane >> 2;

    int acc[NT][4];
    #pragma unroll
    for (int nt = 0; nt < NT; nt++)
        #pragma unroll
        for (int i = 0; i < 4; i++) acc[nt][i] = 0;

    const int4* Ab = Ap + (size_t)rowblk * KT * 64;
    int4 Abuf[PF][2];
    int4 Bbuf[PF][NT];
    #pragma unroll
    for (int j = 0; j < PF; j++) {
        Abuf[j][0] = Ab[j * 64 + lane];
        Abuf[j][1] = Ab[j * 64 + 32 + lane];
        #pragma unroll
        for (int nt = 0; nt < NT; nt++)
            Bbuf[j][nt] = xp[(j * 8 + nt0 + nt) * 32 + lane];
    }

    #pragma unroll 1
    for (int kt0 = 0; kt0 < KT; kt0 += PF) {
        #pragma unroll
        for (int j = 0; j < PF; j++) {
            int kt = kt0 + j;
            int4 cA0 = Abuf[j][0], cA1 = Abuf[j][1];
            int4 cB[NT];
            #pragma unroll
            for (int nt = 0; nt < NT; nt++) cB[nt] = Bbuf[j][nt];
            if (kt + PF < KT) {                   // refill slot j, PF tiles ahead
                Abuf[j][0] = Ab[(kt + PF) * 64 + lane];
                Abuf[j][1] = Ab[(kt + PF) * 64 + 32 + lane];
                #pragma unroll
                for (int nt = 0; nt < NT; nt++)
                    Bbuf[j][nt] = xp[((kt + PF) * 8 + nt0 + nt) * 32 + lane];
            }
            #pragma unroll
            for (int nt = 0; nt < NT; nt++)
                mma_s8(acc[nt], cA0.x, cA1.x, cA0.y, cA1.y, cB[nt].x, cB[nt].y);
            #pragma unroll
            for (int nt = 0; nt < NT; nt++)
                mma_s8(acc[nt], cA0.z, cA1.z, cA0.w, cA1.w, cB[nt].z, cB[nt].w);
        }
    }

    int r0 = rowblk * 16 + l4;
    float w0 = ws[r0], w1 = ws[r0 + 8];
    #pragma unroll
    for (int nt = 0; nt < NT; nt++) {
        int n0 = (nt0 + nt) * 8 + c * 2;
        float s0 = xs[n0], s1 = xs[n0 + 1];
        float v00 = (float)acc[nt][0] * (w0 * s0);
        float v01 = (float)acc[nt][1] * (w0 * s1);
        float v10 = (float)acc[nt][2] * (w1 * s0);
        float v11 = (float)acc[nt][3] * (w1 * s1);
        out[(size_t)n0 * M + r0]           = v00;
        out[(size_t)(n0 + 1) * M + r0]     = v01;
        out[(size_t)n0 * M + r0 + 8]       = v10;
        out[(size_t)(n0 + 1) * M + r0 + 8] = v11;
        if (DOMAX && rowblk >= 256 && rowblk < 528) {   // rows 4096..8447 = xBC slice
            float m0 = fmaxf(fabsf(v00), fabsf(v10));   // batch n0
            float m1 = fmaxf(fabsf(v01), fabsf(v11));   // batch n0+1
            #pragma unroll
            for (int o = 4; o <= 16; o <<= 1) {         // reduce over l4 lanes
                m0 = fmaxf(m0, __shfl_xor_sync(0xFFFFFFFFu, m0, o));
                m1 = fmaxf(m1, __shfl_xor_sync(0xFFFFFFFFu, m1, o));
            }
            if (l4 == 0) {
                atomicMax(&g_xbcmax[n0],     __float_as_int(m0));
                atomicMax(&g_xbcmax[n0 + 1], __float_as_int(m1));
            }
        }
    }
}

// ---------------- K3: state readout + fused k4 epilogue (last block per batch) -------
__global__ void __launch_bounds__(256)
state_kernel(const float* __restrict__ S, const float* __restrict__ dt_bias,
             const float* __restrict__ A_log, const float* __restrict__ Dp) {
    __shared__ float smax[8];
    __shared__ bool  slast;
    __shared__ float s_s2;
    int warp = threadIdx.x >> 5, lane = threadIdx.x & 31;
    int t  = threadIdx.x;
    int wg = blockIdx.x * 8 + warp;  // 0..65535
    int pg = wg & 15;
    int h  = (wg >> 4) & 63;
    int b  = wg >> 10;               // constant within block (128 blocks per batch)

    const float* zb = g_zx + (size_t)b * DINPROJ;
    float sc = __int_as_float(g_xbcmax[b]) / 127.0f;
    if (sc == 0.f) sc = 1.f;

    float4 Cr = ((const float4*)(zb + 2 * DSSM + DSTATE))[lane];
    float4 C4 = make_float4(rintf(Cr.x / sc) * sc, rintf(Cr.y / sc) * sc,
                            rintf(Cr.z / sc) * sc, rintf(Cr.w / sc) * sc);

    const float* Sb = S + (((size_t)b * NHEADS + h) * HEADDIM + pg * 4) * DSTATE;
    float p[4];
    #pragma unroll
    for (int i = 0; i < 4; i++) {
        float4 s4 = ((const float4*)(Sb + i * DSTATE))[lane];
        p[i] = s4.x * C4.x + s4.y * C4.y + s4.z * C4.z + s4.w * C4.w;
    }
    float4 Br = ((const float4*)(zb + 2 * DSSM))[lane];
    float bc = (rintf(Br.x / sc) * sc) * C4.x + (rintf(Br.y / sc) * sc) * C4.y
             + (rintf(Br.z / sc) * sc) * C4.z + (rintf(Br.w / sc) * sc) * C4.w;
    #pragma unroll
    for (int o = 16; o; o >>= 1) {
        #pragma unroll
        for (int i = 0; i < 4; i++) p[i] += __shfl_xor_sync(0xFFFFFFFFu, p[i], o);
        bc += __shfl_xor_sync(0xFFFFFFFFu, bc, o);
    }
    float dtr = zb[2 * DSSM + 2 * DSTATE + h] + dt_bias[h];
    float dts;
    if (dtr < -2.0f)      dts = 0.0f;
    else if (dtr > 2.0f)  dts = dtr;
    else                  dts = 0.69314718055994531f + 0.5f * dtr
                                + (dtr * dtr) / 8.0f + (dtr * dtr * dtr) / 48.0f;
    float A  = -expf(A_log[h]);
    float xA = fmaxf(dts * A, -10000.0f);
    float xA2 = xA * xA, xA3 = xA2 * xA, xA4 = xA3 * xA, xA5 = xA4 * xA;
    float e  = 1.0f + xA + xA2 / 2.0f + xA3 / 6.0f + xA4 / 24.0f + xA5 / 120.0f;
    e = fminf(fmaxf(e, 0.0f), 1.0f);

    float av = 0.f;
    if (lane < 4) {
        float sv = 0.f;
        #pragma unroll
        for (int i = 0; i < 4; i++) if (lane == i) sv = p[i];
        int   pp = pg * 4 + lane;
        float xv = zb[DSSM + h * HEADDIM + pp];
        xv = rintf(xv / sc) * sc;                       // fake-quanted x
        float v = e * sv + dts * bc * xv;
        g_yraw[b * DSSM + h * HEADDIM + pp] = v;
        av = fabsf(v);
    }
    #pragma unroll
    for (int o = 16; o; o >>= 1) av = fmaxf(av, __shfl_xor_sync(0xFFFFFFFFu, av, o));
    if (lane == 0) smax[warp] = av;
    __syncthreads();
    if (t == 0) {
        float m = smax[0];
        #pragma unroll
        for (int i = 1; i < 8; i++) m = fmaxf(m, smax[i]);
        atomicMax(&g_ymax[b], __float_as_int(m));
        __threadfence();                                 // y_raw + ymax visible before arrival
        int old = atomicAdd(&g_cnt[b], 1);
        slast = (old == 127);
    }
    __syncthreads();
    if (!slast) return;

    // ---- last block for batch b: full gated epilogue + quantization (former k4) ----
    __threadfence();                                     // acquire side of the counter
    float s1 = __int_as_float(atomicMax(&g_ymax[b], 0)) / 127.0f;
    if (s1 == 0.f) s1 = 1.f;
    const float4* yq4 = (const float4*)(g_yraw + b * DSSM);
    const float4* zq4 = (const float4*)zb;
    const float4* xq4 = zq4 + DSSM / 4;
    const float4* dq4 = (const float4*)Dp;

    float4 y2v[4];
    float m2 = 0.f;
    #pragma unroll
    for (int j = 0; j < 4; j++) {
        int i = t + j * 256;
        float4 yv = __ldcg(yq4 + i);                     // L2-coherent read of all blocks' writes
        float4 zv = zq4[i], xv = xq4[i], dv = dq4[i];
        float4 y2;
        y2.x = (rintf(yv.x / s1) * s1 + dv.x * (rintf(xv.x / sc) * sc)) * fmaxf(zv.x, 0.f);
        y2.y = (rintf(yv.y / s1) * s1 + dv.y * (rintf(xv.y / sc) * sc)) * fmaxf(zv.y, 0.f);
        y2.z = (rintf(yv.z / s1) * s1 + dv.z * (rintf(xv.z / sc) * sc)) * fmaxf(zv.z, 0.f);
        y2.w = (rintf(yv.w / s1) * s1 + dv.w * (rintf(xv.w / sc) * sc)) * fmaxf(zv.w, 0.f);
        y2v[j] = y2;
        m2 = fmaxf(m2, fmaxf(fmaxf(fabsf(y2.x), fabsf(y2.y)), fmaxf(fabsf(y2.z), fabsf(y2.w))));
    }
    #pragma unroll
    for (int o = 16; o; o >>= 1) m2 = fmaxf(m2, __shfl_xor_sync(0xFFFFFFFFu, m2, o));
    if (lane == 0) smax[warp] = m2;
    __syncthreads();
    if (t == 0) {
        float mm = smax[0];
        #pragma unroll
        for (int i = 1; i < 8; i++) mm = fmaxf(mm, smax[i]);
        float s2 = mm / 127.0f;
        s_s2 = (s2 == 0.f) ? 1.f : s2;
        g_ys[b] = s_s2;                                  // 3rd fake_quant idempotent
        g_cnt[b] = 0;                                    // self-reset for next replay
    }
    __syncthreads();
    float s2 = s_s2;
    #pragma unroll
    for (int j = 0; j < 4; j++) {
        int i = t + j * 256;
        g_yq[bfrag_idx(b, i)] = pack4(y2v[j].x, y2v[j].y, y2v[j].z, y2v[j].w, s2);
    }
}

// ---------------- launch: 5 nodes (4 main + 1 side) ----------------
extern "C" void kernel_launch(void* const* d_in, const int* in_sizes, int n_in,
                              void* d_out, int out_size) {
    (void)in_sizes; (void)n_in; (void)out_size;
    const float* hs   = (const float*)d_in[0];
    const float* ssm  = (const float*)d_in[1];
    const float* Win  = (const float*)d_in[2];
    const float* dtb  = (const float*)d_in[3];
    const float* Alog = (const float*)d_in[4];
    const float* Dp   = (const float*)d_in[5];
    const float* Wout = (const float*)d_in[6];
    float* out = (float*)d_out;

    void *p_xq, *p_xs, *p_wq1, *p_ws1, *p_zx, *p_yq, *p_ys, *p_wq2, *p_ws2;
    cudaGetSymbolAddress(&p_xq,  g_xq);
    cudaGetSymbolAddress(&p_xs,  g_xs);
    cudaGetSymbolAddress(&p_wq1, g_wq1);
    cudaGetSymbolAddress(&p_ws1, g_ws1);
    cudaGetSymbolAddress(&p_zx,  g_zx);
    cudaGetSymbolAddress(&p_yq,  g_yq);
    cudaGetSymbolAddress(&p_ys,  g_ys);
    cudaGetSymbolAddress(&p_wq2, g_wq2);
    cudaGetSymbolAddress(&p_ws2, g_ws2);

    // Streams/events created ONCE on the first (correctness, pre-capture) call and
    // reused during capture -> no allocation during capture (validated in R5).
    static cudaStream_t s2 = nullptr;
    static cudaEvent_t ef, e2;
    if (!s2) {
        cudaStreamCreateWithFlags(&s2, cudaStreamNonBlocking);
        cudaEventCreateWithFlags(&ef, cudaEventDisableTiming);
        cudaEventCreateWithFlags(&e2, cudaEventDisableTiming);
    }

    cudaEventRecord(ef, 0);
    cudaStreamWaitEvent(s2, ef, 0);

    // side: W_out quant (joins before gemm2 — fully off critical path)
    quant_w2_kernel<<<DMODEL / 16, 256, 0, s2>>>(Wout);
    cudaEventRecord(e2, s2);

    // main chain
    prep1_kernel<<<596, 256>>>(hs, Win);
    // GEMM1: 532 rowblocks x NSPLIT=4 -> 2128 warps, 266 blocks of 8 warps
    gemm_imma<DINPROJ, 512, 2, 4, true, 2><<<266, 256>>>(
        (const int4*)p_wq1, (const float*)p_ws1,
        (const int4*)p_xq, (const float*)p_xs, (float*)p_zx);
    state_kernel<<<(NB * NHEADS * 16) / 8, 256>>>(ssm, dtb, Alog, Dp);
    cudaStreamWaitEvent(0, e2, 0);
    // GEMM2: 128 rowblocks x NSPLIT=8 -> 1024 warps, 128 blocks of 8 warps
    gemm_imma<DMODEL, 1024, 1, 8, false, 2><<<128, 256>>>(
        (const int4*)p_wq2, (const float*)p_ws2,
        (const int4*)p_yq, (const float*)p_ys, out);
}

// round 11
// speedup vs baseline: 1.1970x; 1.0806x over previous
#include <cuda_runtime.h>
#include <cstdint>

#define NB      64
#define DMODEL  2048
#define DSSM    4096
#define NHEADS  64
#define HEADDIM 64
#define DSTATE  128
#define DINPROJ 8512   // 2*4096 + 2*128 + 64

// ---------------- scratch (device globals; no allocation) ----------------
__device__ __align__(16) int   g_xq [NB*512];        // hidden quantized, B-FRAGMENT-PERMUTED
__device__            float    g_xs [NB];
__device__ __align__(16) int   g_wq1[DINPROJ*512];   // W_in quantized, A-FRAGMENT-PERMUTED
__device__            float    g_ws1[DINPROJ];
__device__ __align__(16) float g_zx [NB*DINPROJ];    // zxbcdt fp32
__device__ __align__(16) float g_yraw[NB*DSSM];
__device__ __align__(16) int   g_yq [NB*1024];       // y quantized, B-FRAGMENT-PERMUTED
__device__            float    g_ys [NB];
__device__ __align__(16) int   g_wq2[DMODEL*1024];   // W_out quantized, A-FRAGMENT-PERMUTED
__device__            float    g_ws2[DMODEL];
__device__            int      g_xbcmax[NB];         // per-batch max|xBC| (float-as-int)
__device__            int      g_ymax  [NB];         // per-batch max|y_raw|
__device__            int      g_cnt   [NB];         // per-batch arrival counter (self-reset)

// ---------------- helpers ----------------
__device__ __forceinline__ int pack4(float a, float b, float c, float d, float s) {
    int q0 = (int)rintf(a / s);
    int q1 = (int)rintf(b / s);
    int q2 = (int)rintf(c / s);
    int q3 = (int)rintf(d / s);
    return (q0 & 0xFF) | ((q1 & 0xFF) << 8) | ((q2 & 0xFF) << 16) | (q3 << 24);
}

__device__ __forceinline__ void mma_s8(int* c, int a0, int a1, int a2, int a3,
                                       int b0, int b1) {
    asm volatile(
        "mma.sync.aligned.m16n8k32.row.col.s32.s8.s8.s32 "
        "{%0,%1,%2,%3}, {%4,%5,%6,%7}, {%8,%9}, {%0,%1,%2,%3};\n"
        : "+r"(c[0]), "+r"(c[1]), "+r"(c[2]), "+r"(c[3])
        : "r"(a0), "r"(a1), "r"(a2), "r"(a3), "r"(b0), "r"(b1));
}

// B-fragment scatter address (int index) for value covering k[4*j4 .. 4*j4+3] of column b.
__device__ __forceinline__ int bfrag_idx(int b, int j4) {
    int kt = j4 >> 4, comp = (j4 >> 2) & 3, c = j4 & 3;
    int nt = b >> 3, lane = ((b & 7) << 2) + c;
    return ((kt * 8 + nt) * 32 + lane) * 4 + comp;
}

// ---------------- W quantization device function -> A-fragment-permuted layout -------
template<int K>
__device__ __forceinline__ void qw_dev(const float* __restrict__ W, int4* __restrict__ Ap,
                                       float* __restrict__ ws, int bid,
                                       float* sm, float* ssc) {
    const int KT = K / 64;
    int t = threadIdx.x;
    int lane = t & 31, half = (t >> 5) & 1, ktb = t >> 6;   // ktb: 0..3
    int c = lane & 3, rl = (lane >> 2) + half * 8;          // local row 0..15
    int rowg = bid * 16 + rl;
    const float4* Wr = (const float4*)(W + (size_t)rowg * K);

    float m = 0.f;
    for (int kt = ktb; kt < KT; kt += 4) {
        #pragma unroll
        for (int j = 0; j < 4; j++) {
            float4 v = Wr[kt * 16 + c + j * 4];
            m = fmaxf(m, fmaxf(fmaxf(fabsf(v.x), fabsf(v.y)), fmaxf(fabsf(v.z), fabsf(v.w))));
        }
    }
    sm[t] = m; __syncthreads();
    if (t < 16) {
        float mm = 0.f;
        #pragma unroll
        for (int cc = 0; cc < 4; cc++)
            #pragma unroll
            for (int kb = 0; kb < 4; kb++)
                mm = fmaxf(mm, sm[((t & 7) << 2) + cc + ((t >> 3) << 5) + (kb << 6)]);
        float s = mm / 127.0f;
        if (s == 0.f) s = 1.f;
        ssc[t] = s;
        ws[bid * 16 + t] = s;
    }
    __syncthreads();
    float s = ssc[rl];
    int4* outb = Ap + (size_t)bid * KT * 64;
    for (int kt = ktb; kt < KT; kt += 4) {
        int q[4];
        #pragma unroll
        for (int j = 0; j < 4; j++) {
            float4 v = Wr[kt * 16 + c + j * 4];
            q[j] = pack4(v.x, v.y, v.z, v.w, s);
        }
        outb[kt * 64 + half * 32 + lane] = make_int4(q[0], q[1], q[2], q[3]);
    }
}

// ---------------- PREP1 (main stream): W_in quant + quant_x fused ----------------
// blocks [0,532): W_in rowblocks; [532,596): quant_x per batch
__global__ void __launch_bounds__(256)
prep1_kernel(const float* __restrict__ hs, const float* __restrict__ Win) {
    __shared__ float sm[256];
    __shared__ float ssc[16];
    int bid = blockIdx.x, t = threadIdx.x;
    if (bid < 532) {
        qw_dev<DMODEL>(Win, (int4*)g_wq1, g_ws1, bid, sm, ssc);
        return;
    }
    int b = bid - 532;
    if (b == 0 && t < NB) { g_xbcmax[t] = 0; g_ymax[t] = 0; g_cnt[t] = 0; }
    const float* row = hs + b * DMODEL;
    float m = 0.f;
    for (int i = t; i < DMODEL; i += 256) m = fmaxf(m, fabsf(row[i]));
    sm[t] = m; __syncthreads();
    for (int s = 128; s > 0; s >>= 1) { if (t < s) sm[t] = fmaxf(sm[t], sm[t + s]); __syncthreads(); }
    float sc = sm[0] / 127.0f;
    if (sc == 0.f) sc = 1.f;
    if (t == 0) g_xs[b] = sc;
    const float4* row4 = (const float4*)row;
    for (int j4 = t; j4 < 512; j4 += 256) {
        float4 v = row4[j4];
        g_xq[bfrag_idx(b, j4)] = pack4(v.x, v.y, v.z, v.w, sc);
    }
}

// ---------------- W_out quantization (side stream) ----------------
__global__ void __launch_bounds__(256)
quant_w2_kernel(const float* __restrict__ Wout) {
    __shared__ float sm[256];
    __shared__ float ssc[16];
    qw_dev<DSSM>(Wout, (int4*)g_wq2, g_ws2, blockIdx.x, sm, ssc);
}

// ---------------- IMMA GEMM: PF-deep A+B register pipeline ----------------
template<int M, int K4, int NT, int NSPLIT, bool DOMAX, int PF>
__global__ void __launch_bounds__(256)
gemm_imma(const int4* __restrict__ Ap, const float* __restrict__ ws,
          const int4* __restrict__ xp, const float* __restrict__ xs,
          float* __restrict__ out) {
    const int KT = K4 / 16;
    static_assert(KT % PF == 0, "KT must be divisible by PF");
    int warp = threadIdx.x >> 5, lane = threadIdx.x & 31;
    int gw = blockIdx.x * 8 + warp;
    int rowblk = gw / NSPLIT;
    int nt0 = (gw % NSPLIT) * NT;
    int c = lane & 3, l4 = lane >> 2;

    int acc[NT][4];
    #pragma unroll
    for (int nt = 0; nt < NT; nt++)
        #pragma unroll
        for (int i = 0; i < 4; i++) acc[nt][i] = 0;

    const int4* Ab = Ap + (size_t)rowblk * KT * 64;
    int4 Abuf[PF][2];
    int4 Bbuf[PF][NT];
    #pragma unroll
    for (int j = 0; j < PF; j++) {
        Abuf[j][0] = Ab[j * 64 + lane];
        Abuf[j][1] = Ab[j * 64 + 32 + lane];
        #pragma unroll
        for (int nt = 0; nt < NT; nt++)
            Bbuf[j][nt] = xp[(j * 8 + nt0 + nt) * 32 + lane];
    }

    #pragma unroll 1
    for (int kt0 = 0; kt0 < KT; kt0 += PF) {
        #pragma unroll
        for (int j = 0; j < PF; j++) {
            int kt = kt0 + j;
            int4 cA0 = Abuf[j][0], cA1 = Abuf[j][1];
            int4 cB[NT];
            #pragma unroll
            for (int nt = 0; nt < NT; nt++) cB[nt] = Bbuf[j][nt];
            if (kt + PF < KT) {                   // refill slot j, PF tiles ahead
                Abuf[j][0] = Ab[(kt + PF) * 64 + lane];
                Abuf[j][1] = Ab[(kt + PF) * 64 + 32 + lane];
                #pragma unroll
                for (int nt = 0; nt < NT; nt++)
                    Bbuf[j][nt] = xp[((kt + PF) * 8 + nt0 + nt) * 32 + lane];
            }
            #pragma unroll
            for (int nt = 0; nt < NT; nt++)
                mma_s8(acc[nt], cA0.x, cA1.x, cA0.y, cA1.y, cB[nt].x, cB[nt].y);
            #pragma unroll
            for (int nt = 0; nt < NT; nt++)
                mma_s8(acc[nt], cA0.z, cA1.z, cA0.w, cA1.w, cB[nt].z, cB[nt].w);
        }
    }

    int r0 = rowblk * 16 + l4;
    float w0 = ws[r0], w1 = ws[r0 + 8];
    #pragma unroll
    for (int nt = 0; nt < NT; nt++) {
        int n0 = (nt0 + nt) * 8 + c * 2;
        float s0 = xs[n0], s1 = xs[n0 + 1];
        float v00 = (float)acc[nt][0] * (w0 * s0);
        float v01 = (float)acc[nt][1] * (w0 * s1);
        float v10 = (float)acc[nt][2] * (w1 * s0);
        float v11 = (float)acc[nt][3] * (w1 * s1);
        out[(size_t)n0 * M + r0]           = v00;
        out[(size_t)(n0 + 1) * M + r0]     = v01;
        out[(size_t)n0 * M + r0 + 8]       = v10;
        out[(size_t)(n0 + 1) * M + r0 + 8] = v11;
        if (DOMAX && rowblk >= 256 && rowblk < 528) {   // rows 4096..8447 = xBC slice
            float m0 = fmaxf(fabsf(v00), fabsf(v10));   // batch n0
            float m1 = fmaxf(fabsf(v01), fabsf(v11));   // batch n0+1
            #pragma unroll
            for (int o = 4; o <= 16; o <<= 1) {         // reduce over l4 lanes
                m0 = fmaxf(m0, __shfl_xor_sync(0xFFFFFFFFu, m0, o));
                m1 = fmaxf(m1, __shfl_xor_sync(0xFFFFFFFFu, m1, o));
            }
            if (l4 == 0) {
                atomicMax(&g_xbcmax[n0],     __float_as_int(m0));
                atomicMax(&g_xbcmax[n0 + 1], __float_as_int(m1));
            }
        }
    }
}

// ---------------- K3: state readout, per-block hoisted setup + fused k4 epilogue -----
__global__ void __launch_bounds__(256)
state_kernel(const float* __restrict__ S, const float* __restrict__ dt_bias,
             const float* __restrict__ A_log, const float* __restrict__ Dp) {
    __shared__ __align__(16) float sC[DSTATE];   // fake-quanted C (shared by all warps)
    __shared__ float sP[DSTATE];                 // Bq*Cq products
    __shared__ float sX[HEADDIM];                // fake-quanted x for head h
    __shared__ float sScal[3];                   // bc, dts, e
    __shared__ float smax[8];
    __shared__ bool  slast;
    __shared__ float s_s2;

    int t = threadIdx.x;
    int warp = t >> 5, lane = t & 31;
    int blk = blockIdx.x;
    int b  = blk >> 7;                 // 128 blocks per batch
    int h  = (blk >> 1) & 63;
    int pg = ((blk & 1) << 3) + warp;  // 0..15

    const float* zb = g_zx + (size_t)b * DINPROJ;
    float sc = __int_as_float(g_xbcmax[b]) / 127.0f;
    if (sc == 0.f) sc = 1.f;

    // ---- setup (once per block): quantize C, B, x-row; dt/softplus/exp ----
    if (t < DSTATE) {
        float cq = rintf(zb[2 * DSSM + DSTATE + t] / sc) * sc;
        float bq = rintf(zb[2 * DSSM + t] / sc) * sc;
        sC[t] = cq;
        sP[t] = bq * cq;
    } else if (t < DSTATE + HEADDIM) {
        int i = t - DSTATE;
        sX[i] = rintf(zb[DSSM + h * HEADDIM + i] / sc) * sc;
    } else if (t == DSTATE + HEADDIM) {
        float dtr = zb[2 * DSSM + 2 * DSTATE + h] + dt_bias[h];
        float dts;
        if (dtr < -2.0f)      dts = 0.0f;
        else if (dtr > 2.0f)  dts = dtr;
        else                  dts = 0.69314718055994531f + 0.5f * dtr
                                    + (dtr * dtr) / 8.0f + (dtr * dtr * dtr) / 48.0f;
        float A  = -expf(A_log[h]);
        float xA = fmaxf(dts * A, -10000.0f);
        float xA2 = xA * xA, xA3 = xA2 * xA, xA4 = xA3 * xA, xA5 = xA4 * xA;
        float e  = 1.0f + xA + xA2 / 2.0f + xA3 / 6.0f + xA4 / 24.0f + xA5 / 120.0f;
        sScal[1] = dts;
        sScal[2] = fminf(fmaxf(e, 0.0f), 1.0f);
    }
    __syncthreads();
    if (t < 32) {
        float v = sP[t] + sP[t + 32] + sP[t + 64] + sP[t + 96];
        #pragma unroll
        for (int o = 16; o; o >>= 1) v += __shfl_xor_sync(0xFFFFFFFFu, v, o);
        if (t == 0) sScal[0] = v;
    }
    __syncthreads();

    // ---- main: each warp reduces 4 state rows against C ----
    float4 C4 = ((const float4*)sC)[lane];
    const float* Sb = S + (((size_t)b * NHEADS + h) * HEADDIM + pg * 4) * DSTATE;
    float p[4];
    #pragma unroll
    for (int i = 0; i < 4; i++) {
        float4 s4 = __ldcs((const float4*)(Sb + i * DSTATE) + lane);
        p[i] = s4.x * C4.x + s4.y * C4.y + s4.z * C4.z + s4.w * C4.w;
    }
    #pragma unroll
    for (int o = 16; o; o >>= 1) {
        #pragma unroll
        for (int i = 0; i < 4; i++) p[i] += __shfl_xor_sync(0xFFFFFFFFu, p[i], o);
    }
    float bc = sScal[0], dts = sScal[1], e = sScal[2];
    float av = 0.f;
    if (lane < 4) {
        float sv = 0.f;
        #pragma unroll
        for (int i = 0; i < 4; i++) if (lane == i) sv = p[i];
        int pp = pg * 4 + lane;
        float v = e * sv + dts * bc * sX[pp];
        g_yraw[b * DSSM + h * HEADDIM + pp] = v;
        av = fabsf(v);
    }
    #pragma unroll
    for (int o = 16; o; o >>= 1) av = fmaxf(av, __shfl_xor_sync(0xFFFFFFFFu, av, o));
    if (lane == 0) smax[warp] = av;
    __syncthreads();
    if (t == 0) {
        float m = smax[0];
        #pragma unroll
        for (int i = 1; i < 8; i++) m = fmaxf(m, smax[i]);
        atomicMax(&g_ymax[b], __float_as_int(m));
        __threadfence();                                 // y_raw + ymax visible before arrival
        int old = atomicAdd(&g_cnt[b], 1);
        slast = (old == 127);
    }
    __syncthreads();
    if (!slast) return;

    // ---- last block for batch b: full gated epilogue + quantization (former k4) ----
    __threadfence();                                     // acquire side of the counter
    float s1 = __int_as_float(atomicMax(&g_ymax[b], 0)) / 127.0f;
    if (s1 == 0.f) s1 = 1.f;
    const float4* yq4 = (const float4*)(g_yraw + b * DSSM);
    const float4* zq4 = (const float4*)zb;
    const float4* xq4 = zq4 + DSSM / 4;
    const float4* dq4 = (const float4*)Dp;

    float4 y2v[4];
    float m2 = 0.f;
    #pragma unroll
    for (int j = 0; j < 4; j++) {
        int i = t + j * 256;
        float4 yv = __ldcg(yq4 + i);                     // L2-coherent read of all blocks' writes
        float4 zv = zq4[i], xv = xq4[i], dv = dq4[i];
        float4 y2;
        y2.x = (rintf(yv.x / s1) * s1 + dv.x * (rintf(xv.x / sc) * sc)) * fmaxf(zv.x, 0.f);
        y2.y = (rintf(yv.y / s1) * s1 + dv.y * (rintf(xv.y / sc) * sc)) * fmaxf(zv.y, 0.f);
        y2.z = (rintf(yv.z / s1) * s1 + dv.z * (rintf(xv.z / sc) * sc)) * fmaxf(zv.z, 0.f);
        y2.w = (rintf(yv.w / s1) * s1 + dv.w * (rintf(xv.w / sc) * sc)) * fmaxf(zv.w, 0.f);
        y2v[j] = y2;
        m2 = fmaxf(m2, fmaxf(fmaxf(fabsf(y2.x), fabsf(y2.y)), fmaxf(fabsf(y2.z), fabsf(y2.w))));
    }
    #pragma unroll
    for (int o = 16; o; o >>= 1) m2 = fmaxf(m2, __shfl_xor_sync(0xFFFFFFFFu, m2, o));
    if (lane == 0) smax[warp] = m2;
    __syncthreads();
    if (t == 0) {
        float mm = smax[0];
        #pragma unroll
        for (int i = 1; i < 8; i++) mm = fmaxf(mm, smax[i]);
        float s2 = mm / 127.0f;
        s_s2 = (s2 == 0.f) ? 1.f : s2;
        g_ys[b] = s_s2;                                  // 3rd fake_quant idempotent
        g_cnt[b] = 0;                                    // self-reset for next replay
    }
    __syncthreads();
    float s2 = s_s2;
    #pragma unroll
    for (int j = 0; j < 4; j++) {
        int i = t + j * 256;
        g_yq[bfrag_idx(b, i)] = pack4(y2v[j].x, y2v[j].y, y2v[j].z, y2v[j].w, s2);
    }
}

// ---------------- launch: 5 nodes (4 main + 1 side) ----------------
extern "C" void kernel_launch(void* const* d_in, const int* in_sizes, int n_in,
                              void* d_out, int out_size) {
    (void)in_sizes; (void)n_in; (void)out_size;
    const float* hs   = (const float*)d_in[0];
    const float* ssm  = (const float*)d_in[1];
    const float* Win  = (const float*)d_in[2];
    const float* dtb  = (const float*)d_in[3];
    const float* Alog = (const float*)d_in[4];
    const float* Dp   = (const float*)d_in[5];
    const float* Wout = (const float*)d_in[6];
    float* out = (float*)d_out;

    void *p_xq, *p_xs, *p_wq1, *p_ws1, *p_zx, *p_yq, *p_ys, *p_wq2, *p_ws2;
    cudaGetSymbolAddress(&p_xq,  g_xq);
    cudaGetSymbolAddress(&p_xs,  g_xs);
    cudaGetSymbolAddress(&p_wq1, g_wq1);
    cudaGetSymbolAddress(&p_ws1, g_ws1);
    cudaGetSymbolAddress(&p_zx,  g_zx);
    cudaGetSymbolAddress(&p_yq,  g_yq);
    cudaGetSymbolAddress(&p_ys,  g_ys);
    cudaGetSymbolAddress(&p_wq2, g_wq2);
    cudaGetSymbolAddress(&p_ws2, g_ws2);

    // Streams/events created ONCE on the first (correctness, pre-capture) call and
    // reused during capture -> no allocation during capture (validated in R5).
    static cudaStream_t s2 = nullptr;
    static cudaEvent_t ef, e2;
    if (!s2) {
        cudaStreamCreateWithFlags(&s2, cudaStreamNonBlocking);
        cudaEventCreateWithFlags(&ef, cudaEventDisableTiming);
        cudaEventCreateWithFlags(&e2, cudaEventDisableTiming);
    }

    cudaEventRecord(ef, 0);
    cudaStreamWaitEvent(s2, ef, 0);

    // side: W_out quant (joins before gemm2 — fully off critical path)
    quant_w2_kernel<<<DMODEL / 16, 256, 0, s2>>>(Wout);
    cudaEventRecord(e2, s2);

    // main chain
    prep1_kernel<<<596, 256>>>(hs, Win);
    // GEMM1: 532 rowblocks x NSPLIT=4 -> 2128 warps, 266 blocks of 8 warps
    gemm_imma<DINPROJ, 512, 2, 4, true, 2><<<266, 256>>>(
        (const int4*)p_wq1, (const float*)p_ws1,
        (const int4*)p_xq, (const float*)p_xs, (float*)p_zx);
    state_kernel<<<NB * 128, 256>>>(ssm, dtb, Alog, Dp);
    cudaStreamWaitEvent(0, e2, 0);
    // GEMM2: 128 rowblocks x NSPLIT=8 -> 1024 warps, 128 blocks of 8 warps
    gemm_imma<DMODEL, 1024, 1, 8, false, 2><<<128, 256>>>(
        (const int4*)p_wq2, (const float*)p_ws2,
        (const int4*)p_yq, (const float*)p_ys, out);
}

// round 12
// speedup vs baseline: 1.3480x; 1.1262x over previous
#include <cuda_runtime.h>
#include <cstdint>

#define NB      64
#define DMODEL  2048
#define DSSM    4096
#define NHEADS  64
#define HEADDIM 64
#define DSTATE  128
#define DINPROJ 8512   // 2*4096 + 2*128 + 64

// ---------------- scratch (device globals; no allocation) ----------------
__device__ __align__(16) int   g_xq [NB*512];        // hidden quantized, B-FRAGMENT-PERMUTED
__device__            float    g_xs [NB];
__device__ __align__(16) int   g_wq1[DINPROJ*512];   // W_in quantized, A-FRAGMENT-PERMUTED
__device__            float    g_ws1[DINPROJ];
__device__ __align__(16) float g_zx [NB*DINPROJ];    // zxbcdt fp32
__device__ __align__(16) float g_yraw[NB*DSSM];
__device__ __align__(16) int   g_yq [NB*1024];       // y quantized, B-FRAGMENT-PERMUTED
__device__            float    g_ys [NB];
__device__ __align__(16) int   g_wq2[DMODEL*1024];   // W_out quantized, A-FRAGMENT-PERMUTED
__device__            float    g_ws2[DMODEL];
__device__            int      g_xbcmax[NB];         // per-batch max|xBC| (float-as-int)
__device__            int      g_ymax  [NB];         // per-batch max|y_raw|
__device__            int      g_cnt   [NB];         // per-batch arrival counter (self-reset)

// ---------------- helpers ----------------
__device__ __forceinline__ int pack4(float a, float b, float c, float d, float s) {
    int q0 = (int)rintf(a / s);
    int q1 = (int)rintf(b / s);
    int q2 = (int)rintf(c / s);
    int q3 = (int)rintf(d / s);
    return (q0 & 0xFF) | ((q1 & 0xFF) << 8) | ((q2 & 0xFF) << 16) | (q3 << 24);
}

__device__ __forceinline__ void mma_s8(int* c, int a0, int a1, int a2, int a3,
                                       int b0, int b1) {
    asm volatile(
        "mma.sync.aligned.m16n8k32.row.col.s32.s8.s8.s32 "
        "{%0,%1,%2,%3}, {%4,%5,%6,%7}, {%8,%9}, {%0,%1,%2,%3};\n"
        : "+r"(c[0]), "+r"(c[1]), "+r"(c[2]), "+r"(c[3])
        : "r"(a0), "r"(a1), "r"(a2), "r"(a3), "r"(b0), "r"(b1));
}

// B-fragment scatter address (int index) for value covering k[4*j4 .. 4*j4+3] of column b.
__device__ __forceinline__ int bfrag_idx(int b, int j4) {
    int kt = j4 >> 4, comp = (j4 >> 2) & 3, c = j4 & 3;
    int nt = b >> 3, lane = ((b & 7) << 2) + c;
    return ((kt * 8 + nt) * 32 + lane) * 4 + comp;
}

// ---------------- W quantization device function -> A-fragment-permuted layout -------
template<int K>
__device__ __forceinline__ void qw_dev(const float* __restrict__ W, int4* __restrict__ Ap,
                                       float* __restrict__ ws, int bid,
                                       float* sm, float* ssc) {
    const int KT = K / 64;
    int t = threadIdx.x;
    int lane = t & 31, half = (t >> 5) & 1, ktb = t >> 6;   // ktb: 0..3
    int c = lane & 3, rl = (lane >> 2) + half * 8;          // local row 0..15
    int rowg = bid * 16 + rl;
    const float4* Wr = (const float4*)(W + (size_t)rowg * K);

    float m = 0.f;
    for (int kt = ktb; kt < KT; kt += 4) {
        #pragma unroll
        for (int j = 0; j < 4; j++) {
            float4 v = Wr[kt * 16 + c + j * 4];
            m = fmaxf(m, fmaxf(fmaxf(fabsf(v.x), fabsf(v.y)), fmaxf(fabsf(v.z), fabsf(v.w))));
        }
    }
    sm[t] = m; __syncthreads();
    if (t < 16) {
        float mm = 0.f;
        #pragma unroll
        for (int cc = 0; cc < 4; cc++)
            #pragma unroll
            for (int kb = 0; kb < 4; kb++)
                mm = fmaxf(mm, sm[((t & 7) << 2) + cc + ((t >> 3) << 5) + (kb << 6)]);
        float s = mm / 127.0f;
        if (s == 0.f) s = 1.f;
        ssc[t] = s;
        ws[bid * 16 + t] = s;
    }
    __syncthreads();
    float s = ssc[rl];
    int4* outb = Ap + (size_t)bid * KT * 64;
    for (int kt = ktb; kt < KT; kt += 4) {
        int q[4];
        #pragma unroll
        for (int j = 0; j < 4; j++) {
            float4 v = Wr[kt * 16 + c + j * 4];
            q[j] = pack4(v.x, v.y, v.z, v.w, s);
        }
        outb[kt * 64 + half * 32 + lane] = make_int4(q[0], q[1], q[2], q[3]);
    }
}

// ---------------- PREP1 (main stream): W_in quant + quant_x fused ----------------
// blocks [0,532): W_in rowblocks; [532,596): quant_x per batch
__global__ void __launch_bounds__(256)
prep1_kernel(const float* __restrict__ hs, const float* __restrict__ Win) {
    __shared__ float sm[256];
    __shared__ float ssc[16];
    int bid = blockIdx.x, t = threadIdx.x;
    if (bid < 532) {
        qw_dev<DMODEL>(Win, (int4*)g_wq1, g_ws1, bid, sm, ssc);
        return;
    }
    int b = bid - 532;
    if (b == 0 && t < NB) { g_xbcmax[t] = 0; g_ymax[t] = 0; g_cnt[t] = 0; }
    const float* row = hs + b * DMODEL;
    float m = 0.f;
    for (int i = t; i < DMODEL; i += 256) m = fmaxf(m, fabsf(row[i]));
    sm[t] = m; __syncthreads();
    for (int s = 128; s > 0; s >>= 1) { if (t < s) sm[t] = fmaxf(sm[t], sm[t + s]); __syncthreads(); }
    float sc = sm[0] / 127.0f;
    if (sc == 0.f) sc = 1.f;
    if (t == 0) g_xs[b] = sc;
    const float4* row4 = (const float4*)row;
    for (int j4 = t; j4 < 512; j4 += 256) {
        float4 v = row4[j4];
        g_xq[bfrag_idx(b, j4)] = pack4(v.x, v.y, v.z, v.w, sc);
    }
}

// ---------------- W_out quantization (side stream) ----------------
__global__ void __launch_bounds__(256)
quant_w2_kernel(const float* __restrict__ Wout) {
    __shared__ float sm[256];
    __shared__ float ssc[16];
    qw_dev<DSSM>(Wout, (int4*)g_wq2, g_ws2, blockIdx.x, sm, ssc);
}

// ---------------- IMMA GEMM: PF-deep A+B register pipeline ----------------
template<int M, int K4, int NT, int NSPLIT, bool DOMAX, int PF>
__global__ void __launch_bounds__(256)
gemm_imma(const int4* __restrict__ Ap, const float* __restrict__ ws,
          const int4* __restrict__ xp, const float* __restrict__ xs,
          float* __restrict__ out) {
    const int KT = K4 / 16;
    static_assert(KT % PF == 0, "KT must be divisible by PF");
    int warp = threadIdx.x >> 5, lane = threadIdx.x & 31;
    int gw = blockIdx.x * 8 + warp;
    int rowblk = gw / NSPLIT;
    int nt0 = (gw % NSPLIT) * NT;
    int c = lane & 3, l4 = lane >> 2;

    int acc[NT][4];
    #pragma unroll
    for (int nt = 0; nt < NT; nt++)
        #pragma unroll
        for (int i = 0; i < 4; i++) acc[nt][i] = 0;

    const int4* Ab = Ap + (size_t)rowblk * KT * 64;
    int4 Abuf[PF][2];
    int4 Bbuf[PF][NT];
    #pragma unroll
    for (int j = 0; j < PF; j++) {
        Abuf[j][0] = Ab[j * 64 + lane];
        Abuf[j][1] = Ab[j * 64 + 32 + lane];
        #pragma unroll
        for (int nt = 0; nt < NT; nt++)
            Bbuf[j][nt] = xp[(j * 8 + nt0 + nt) * 32 + lane];
    }

    #pragma unroll 1
    for (int kt0 = 0; kt0 < KT; kt0 += PF) {
        #pragma unroll
        for (int j = 0; j < PF; j++) {
            int kt = kt0 + j;
            int4 cA0 = Abuf[j][0], cA1 = Abuf[j][1];
            int4 cB[NT];
            #pragma unroll
            for (int nt = 0; nt < NT; nt++) cB[nt] = Bbuf[j][nt];
            if (kt + PF < KT) {                   // refill slot j, PF tiles ahead
                Abuf[j][0] = Ab[(kt + PF) * 64 + lane];
                Abuf[j][1] = Ab[(kt + PF) * 64 + 32 + lane];
                #pragma unroll
                for (int nt = 0; nt < NT; nt++)
                    Bbuf[j][nt] = xp[((kt + PF) * 8 + nt0 + nt) * 32 + lane];
            }
            #pragma unroll
            for (int nt = 0; nt < NT; nt++)
                mma_s8(acc[nt], cA0.x, cA1.x, cA0.y, cA1.y, cB[nt].x, cB[nt].y);
            #pragma unroll
            for (int nt = 0; nt < NT; nt++)
                mma_s8(acc[nt], cA0.z, cA1.z, cA0.w, cA1.w, cB[nt].z, cB[nt].w);
        }
    }

    int r0 = rowblk * 16 + l4;
    float w0 = ws[r0], w1 = ws[r0 + 8];
    #pragma unroll
    for (int nt = 0; nt < NT; nt++) {
        int n0 = (nt0 + nt) * 8 + c * 2;
        float s0 = xs[n0], s1 = xs[n0 + 1];
        float v00 = (float)acc[nt][0] * (w0 * s0);
        float v01 = (float)acc[nt][1] * (w0 * s1);
        float v10 = (float)acc[nt][2] * (w1 * s0);
        float v11 = (float)acc[nt][3] * (w1 * s1);
        out[(size_t)n0 * M + r0]           = v00;
        out[(size_t)(n0 + 1) * M + r0]     = v01;
        out[(size_t)n0 * M + r0 + 8]       = v10;
        out[(size_t)(n0 + 1) * M + r0 + 8] = v11;
        if (DOMAX && rowblk >= 256 && rowblk < 528) {   // rows 4096..8447 = xBC slice
            float m0 = fmaxf(fabsf(v00), fabsf(v10));   // batch n0
            float m1 = fmaxf(fabsf(v01), fabsf(v11));   // batch n0+1
            #pragma unroll
            for (int o = 4; o <= 16; o <<= 1) {         // reduce over l4 lanes
                m0 = fmaxf(m0, __shfl_xor_sync(0xFFFFFFFFu, m0, o));
                m1 = fmaxf(m1, __shfl_xor_sync(0xFFFFFFFFu, m1, o));
            }
            if (l4 == 0) {
                atomicMax(&g_xbcmax[n0],     __float_as_int(m0));
                atomicMax(&g_xbcmax[n0 + 1], __float_as_int(m1));
            }
        }
    }
}

// ---------------- K3: state readout, 8 rows/warp (one head per block) ----------------
__global__ void __launch_bounds__(256)
state_kernel(const float* __restrict__ S, const float* __restrict__ dt_bias,
             const float* __restrict__ A_log, const float* __restrict__ Dp) {
    __shared__ __align__(16) float sC[DSTATE];   // fake-quanted C (shared by all warps)
    __shared__ float sP[DSTATE];                 // Bq*Cq products
    __shared__ float sX[HEADDIM];                // fake-quanted x for head h
    __shared__ float sScal[3];                   // bc, dts, e
    __shared__ float smax[8];
    __shared__ bool  slast;
    __shared__ float s_s2;

    int t = threadIdx.x;
    int warp = t >> 5, lane = t & 31;
    int blk = blockIdx.x;
    int b  = blk >> 6;                 // 64 blocks per batch (one head each)
    int h  = blk & 63;

    const float* zb = g_zx + (size_t)b * DINPROJ;
    float sc = __int_as_float(g_xbcmax[b]) / 127.0f;
    if (sc == 0.f) sc = 1.f;

    // ---- setup (once per block): quantize C, B, x-row; dt/softplus/exp ----
    if (t < DSTATE) {
        float cq = rintf(zb[2 * DSSM + DSTATE + t] / sc) * sc;
        float bq = rintf(zb[2 * DSSM + t] / sc) * sc;
        sC[t] = cq;
        sP[t] = bq * cq;
    } else if (t < DSTATE + HEADDIM) {
        int i = t - DSTATE;
        sX[i] = rintf(zb[DSSM + h * HEADDIM + i] / sc) * sc;
    } else if (t == DSTATE + HEADDIM) {
        float dtr = zb[2 * DSSM + 2 * DSTATE + h] + dt_bias[h];
        float dts;
        if (dtr < -2.0f)      dts = 0.0f;
        else if (dtr > 2.0f)  dts = dtr;
        else                  dts = 0.69314718055994531f + 0.5f * dtr
                                    + (dtr * dtr) / 8.0f + (dtr * dtr * dtr) / 48.0f;
        float A  = -expf(A_log[h]);
        float xA = fmaxf(dts * A, -10000.0f);
        float xA2 = xA * xA, xA3 = xA2 * xA, xA4 = xA3 * xA, xA5 = xA4 * xA;
        float e  = 1.0f + xA + xA2 / 2.0f + xA3 / 6.0f + xA4 / 24.0f + xA5 / 120.0f;
        sScal[1] = dts;
        sScal[2] = fminf(fmaxf(e, 0.0f), 1.0f);
    }
    __syncthreads();
    if (t < 32) {
        float v = sP[t] + sP[t + 32] + sP[t + 64] + sP[t + 96];
        #pragma unroll
        for (int o = 16; o; o >>= 1) v += __shfl_xor_sync(0xFFFFFFFFu, v, o);
        if (t == 0) sScal[0] = v;
    }
    __syncthreads();

    // ---- main: each warp reduces 8 state rows against C (8 loads in flight) ----
    float4 C4 = ((const float4*)sC)[lane];
    const float* Sb = S + (((size_t)b * NHEADS + h) * HEADDIM + warp * 8) * DSTATE;
    float4 sv4[8];
    #pragma unroll
    for (int i = 0; i < 8; i++)
        sv4[i] = __ldcs((const float4*)(Sb + i * DSTATE) + lane);
    float p[8];
    #pragma unroll
    for (int i = 0; i < 8; i++)
        p[i] = sv4[i].x * C4.x + sv4[i].y * C4.y + sv4[i].z * C4.z + sv4[i].w * C4.w;
    #pragma unroll
    for (int o = 16; o; o >>= 1) {
        #pragma unroll
        for (int i = 0; i < 8; i++) p[i] += __shfl_xor_sync(0xFFFFFFFFu, p[i], o);
    }
    float bc = sScal[0], dts = sScal[1], e = sScal[2];
    float av = 0.f;
    if (lane < 8) {
        float sv = 0.f;
        #pragma unroll
        for (int i = 0; i < 8; i++) if (lane == i) sv = p[i];
        int pp = warp * 8 + lane;
        float v = e * sv + dts * bc * sX[pp];
        g_yraw[b * DSSM + h * HEADDIM + pp] = v;
        av = fabsf(v);
    }
    #pragma unroll
    for (int o = 16; o; o >>= 1) av = fmaxf(av, __shfl_xor_sync(0xFFFFFFFFu, av, o));
    if (lane == 0) smax[warp] = av;
    __syncthreads();
    if (t == 0) {
        float m = smax[0];
        #pragma unroll
        for (int i = 1; i < 8; i++) m = fmaxf(m, smax[i]);
        atomicMax(&g_ymax[b], __float_as_int(m));
        __threadfence();                                 // y_raw + ymax visible before arrival
        int old = atomicAdd(&g_cnt[b], 1);
        slast = (old == 63);
    }
    __syncthreads();
    if (!slast) return;

    // ---- last block for batch b: full gated epilogue + quantization (former k4) ----
    __threadfence();                                     // acquire side of the counter
    float s1 = __int_as_float(atomicMax(&g_ymax[b], 0)) / 127.0f;
    if (s1 == 0.f) s1 = 1.f;
    const float4* yq4 = (const float4*)(g_yraw + b * DSSM);
    const float4* zq4 = (const float4*)zb;
    const float4* xq4 = zq4 + DSSM / 4;
    const float4* dq4 = (const float4*)Dp;

    float4 y2v[4];
    float m2 = 0.f;
    #pragma unroll
    for (int j = 0; j < 4; j++) {
        int i = t + j * 256;
        float4 yv = __ldcg(yq4 + i);                     // L2-coherent read of all blocks' writes
        float4 zv = zq4[i], xv = xq4[i], dv = dq4[i];
        float4 y2;
        y2.x = (rintf(yv.x / s1) * s1 + dv.x * (rintf(xv.x / sc) * sc)) * fmaxf(zv.x, 0.f);
        y2.y = (rintf(yv.y / s1) * s1 + dv.y * (rintf(xv.y / sc) * sc)) * fmaxf(zv.y, 0.f);
        y2.z = (rintf(yv.z / s1) * s1 + dv.z * (rintf(xv.z / sc) * sc)) * fmaxf(zv.z, 0.f);
        y2.w = (rintf(yv.w / s1) * s1 + dv.w * (rintf(xv.w / sc) * sc)) * fmaxf(zv.w, 0.f);
        y2v[j] = y2;
        m2 = fmaxf(m2, fmaxf(fmaxf(fabsf(y2.x), fabsf(y2.y)), fmaxf(fabsf(y2.z), fabsf(y2.w))));
    }
    #pragma unroll
    for (int o = 16; o; o >>= 1) m2 = fmaxf(m2, __shfl_xor_sync(0xFFFFFFFFu, m2, o));
    if (lane == 0) smax[warp] = m2;
    __syncthreads();
    if (t == 0) {
        float mm = smax[0];
        #pragma unroll
        for (int i = 1; i < 8; i++) mm = fmaxf(mm, smax[i]);
        float s2 = mm / 127.0f;
        s_s2 = (s2 == 0.f) ? 1.f : s2;
        g_ys[b] = s_s2;                                  // 3rd fake_quant idempotent
        g_cnt[b] = 0;                                    // self-reset for next replay
    }
    __syncthreads();
    float s2 = s_s2;
    #pragma unroll
    for (int j = 0; j < 4; j++) {
        int i = t + j * 256;
        g_yq[bfrag_idx(b, i)] = pack4(y2v[j].x, y2v[j].y, y2v[j].z, y2v[j].w, s2);
    }
}

// ---------------- launch: 5 nodes (4 main + 1 side) ----------------
extern "C" void kernel_launch(void* const* d_in, const int* in_sizes, int n_in,
                              void* d_out, int out_size) {
    (void)in_sizes; (void)n_in; (void)out_size;
    const float* hs   = (const float*)d_in[0];
    const float* ssm  = (const float*)d_in[1];
    const float* Win  = (const float*)d_in[2];
    const float* dtb  = (const float*)d_in[3];
    const float* Alog = (const float*)d_in[4];
    const float* Dp   = (const float*)d_in[5];
    const float* Wout = (const float*)d_in[6];
    float* out = (float*)d_out;

    void *p_xq, *p_xs, *p_wq1, *p_ws1, *p_zx, *p_yq, *p_ys, *p_wq2, *p_ws2;
    cudaGetSymbolAddress(&p_xq,  g_xq);
    cudaGetSymbolAddress(&p_xs,  g_xs);
    cudaGetSymbolAddress(&p_wq1, g_wq1);
    cudaGetSymbolAddress(&p_ws1, g_ws1);
    cudaGetSymbolAddress(&p_zx,  g_zx);
    cudaGetSymbolAddress(&p_yq,  g_yq);
    cudaGetSymbolAddress(&p_ys,  g_ys);
    cudaGetSymbolAddress(&p_wq2, g_wq2);
    cudaGetSymbolAddress(&p_ws2, g_ws2);

    // Streams/events created ONCE on the first (correctness, pre-capture) call and
    // reused during capture -> no allocation during capture (validated in R5).
    static cudaStream_t s2 = nullptr;
    static cudaEvent_t ef, e2;
    if (!s2) {
        cudaStreamCreateWithFlags(&s2, cudaStreamNonBlocking);
        cudaEventCreateWithFlags(&ef, cudaEventDisableTiming);
        cudaEventCreateWithFlags(&e2, cudaEventDisableTiming);
    }

    cudaEventRecord(ef, 0);
    cudaStreamWaitEvent(s2, ef, 0);

    // side: W_out quant (joins before gemm2 — fully off critical path)
    quant_w2_kernel<<<DMODEL / 16, 256, 0, s2>>>(Wout);
    cudaEventRecord(e2, s2);

    // main chain
    prep1_kernel<<<596, 256>>>(hs, Win);
    // GEMM1: 532 rowblocks x NSPLIT=4 -> 2128 warps, 266 blocks of 8 warps
    gemm_imma<DINPROJ, 512, 2, 4, true, 2><<<266, 256>>>(
        (const int4*)p_wq1, (const float*)p_ws1,
        (const int4*)p_xq, (const float*)p_xs, (float*)p_zx);
    state_kernel<<<NB * 64, 256>>>(ssm, dtb, Alog, Dp);
    cudaStreamWaitEvent(0, e2, 0);
    // GEMM2: 128 rowblocks x NSPLIT=8 -> 1024 warps, 128 blocks of 8 warps
    gemm_imma<DMODEL, 1024, 1, 8, false, 2><<<128, 256>>>(
        (const int4*)p_wq2, (const float*)p_ws2,
        (const int4*)p_yq, (const float*)p_ys, out);
}